// round 5
// baseline (speedup 1.0000x reference)
#include <cuda_runtime.h>

#define Nn 100000
#define Ee 1200000
#define Dd 64
#define NGIN 4
#define NPRED 5
#define NG 512

typedef unsigned long long ull;

__device__ __forceinline__ ull dup2(float x){
    ull r; asm("mov.b64 %0, {%1, %1};" : "=l"(r) : "f"(x)); return r;
}
__device__ __forceinline__ void fma2(ull &d, ull a, ull b){
    asm("fma.rn.f32x2 %0, %1, %2, %0;" : "+l"(d) : "l"(a), "l"(b));
}
__device__ __forceinline__ float2 u2f2(ull v){
    float2 f; asm("mov.b64 {%0, %1}, %2;" : "=f"(f.x), "=f"(f.y) : "l"(v)); return f;
}

// ---------------- scratch ----------------
__device__ float g_pre[Nn*Dd];      // aggregation output
__device__ float g_t[Nn*Dd];        // GEMM1 output
__device__ float g_u[Nn*Dd];        // GEMM2 output (pre-BN)
__device__ int   g_deg[Nn];
__device__ int   g_rowptr[Nn+1];
__device__ int   g_cursor[Nn];
__device__ int   g_col[Ee];
__device__ int   g_flag[128];       // scan lookback flags (zeroed in k_hist)
__device__ int   g_run[128];        // inclusive running sums
__device__ float g_stats[8*128];    // 8 slots: [0:64) sum, [64:128) sumsq
__device__ float g_pooled[NPRED*NG*Dd];

// ---------------- CSR build (+ fold all zeroing in) ----------------
__global__ void k_hist(const int* __restrict__ dst){
    int i = blockIdx.x*blockDim.x + threadIdx.x;
    if (i < Ee) atomicAdd(&g_deg[dst[i]], 1);
    if (i < NPRED*NG*Dd) g_pooled[i] = 0.f;
    if (i < 8*128) g_stats[i] = 0.f;
    if (i < 128){ g_flag[i] = 0; }
}

// single-kernel chained scan: grid=98 blocks (all resident on 148 SMs), block=1024
__global__ void k_scan(){
    __shared__ int s[1024];
    __shared__ int sExcl;
    int b = blockIdx.x;
    int i = b*1024 + threadIdx.x;
    int v = 0;
    if (i < Nn){ v = g_deg[i]; g_deg[i] = 0; }   // self-clean for next replay
    s[threadIdx.x] = v;
    #pragma unroll
    for (int off = 1; off < 1024; off <<= 1){
        __syncthreads();
        int x = (threadIdx.x >= off) ? s[threadIdx.x - off] : 0;
        __syncthreads();
        s[threadIdx.x] += x;
    }
    if (threadIdx.x == 1023){
        int total = s[1023];
        int excl = 0;
        if (b > 0){
            while (atomicAdd(&g_flag[b-1], 0) == 0) { }
            excl = atomicAdd(&g_run[b-1], 0);
        }
        atomicExch(&g_run[b], excl + total);
        __threadfence();
        atomicExch(&g_flag[b], 1);
        sExcl = excl;
    }
    __syncthreads();
    int excl = sExcl;
    if (i < Nn){
        int val = s[threadIdx.x] + excl;
        g_rowptr[i+1] = val;
        if (i+1 < Nn) g_cursor[i+1] = val;
    }
    if (i == 0){ g_rowptr[0] = 0; g_cursor[0] = 0; }
}

__global__ void k_scatter(const int* __restrict__ src, const int* __restrict__ dst){
    int i = blockIdx.x*blockDim.x + threadIdx.x;
    if (i < Ee){
        int p = atomicAdd(&g_cursor[dst[i]], 1);
        g_col[p] = src[i];
    }
}

// ---------------- per-block BN coefficient computation (redundant, cheap) ----------------
__device__ __forceinline__ void bn_coeffs(const float* __restrict__ stats,
                                          const float* __restrict__ gamma,
                                          const float* __restrict__ beta,
                                          float* sA, float* sB, int tid)
{
    if (tid < 64){
        float m = stats[tid]    * (1.f/Nn);
        float v = stats[64+tid] * (1.f/Nn) - m*m;
        float a = gamma[tid] * rsqrtf(v + 1e-5f);
        sA[tid] = a;
        sB[tid] = beta[tid] - m*a;
    }
}

// ---------------- aggregation (warp per node) with fused BN+relu on the source
// AND fused sum-pooling of the BN'd self value (= hidden_rep[layer]) ----------------
template<int MODE>
__global__ void __launch_bounds__(256) k_agg(const float* __restrict__ hin,
                                             const float* __restrict__ eps, int layer,
                                             const int* __restrict__ gid,
                                             float* __restrict__ pooled,
                                             const float* __restrict__ statsIn,
                                             const float* __restrict__ gamma,
                                             const float* __restrict__ beta)
{
    __shared__ float sA[64], sB[64];
    __shared__ float sPool[8][64];
    __shared__ int   sGid[8];
    int tid  = threadIdx.x;
    int wp   = tid >> 5;
    int lane = tid & 31;
    int w    = blockIdx.x*8 + wp;            // node; Nn % 8 == 0 -> always valid

    if (MODE){
        bn_coeffs(statsIn, gamma, beta, sA, sB, tid);
        __syncthreads();
    }

    const float2* __restrict__ h2 = (const float2*)hin;
    float Ax=1.f, Ay=1.f, Bx=0.f, By=0.f;
    if (MODE){
        Ax = sA[2*lane]; Ay = sA[2*lane+1];
        Bx = sB[2*lane]; By = sB[2*lane+1];
    }
    float epv = 1.f + eps[layer];

    float2 s = h2[w*32 + lane];
    float fx = s.x, fy = s.y;
    if (MODE){ fx = fmaxf(fmaf(fx,Ax,Bx),0.f); fy = fmaxf(fmaf(fy,Ay,By),0.f); }
    sPool[wp][2*lane]   = fx;
    sPool[wp][2*lane+1] = fy;
    if (lane == 0) sGid[wp] = gid[w];

    float ax = fx * epv, ay = fy * epv;
    int e = g_rowptr[w], end = g_rowptr[w+1];
    for (; e + 4 <= end; e += 4){
        int s0 = g_col[e], s1 = g_col[e+1], s2 = g_col[e+2], s3 = g_col[e+3];
        float2 v0 = h2[s0*32+lane], v1 = h2[s1*32+lane];
        float2 v2 = h2[s2*32+lane], v3 = h2[s3*32+lane];
        if (MODE){
            v0.x = fmaxf(fmaf(v0.x,Ax,Bx),0.f); v0.y = fmaxf(fmaf(v0.y,Ay,By),0.f);
            v1.x = fmaxf(fmaf(v1.x,Ax,Bx),0.f); v1.y = fmaxf(fmaf(v1.y,Ay,By),0.f);
            v2.x = fmaxf(fmaf(v2.x,Ax,Bx),0.f); v2.y = fmaxf(fmaf(v2.y,Ay,By),0.f);
            v3.x = fmaxf(fmaf(v3.x,Ax,Bx),0.f); v3.y = fmaxf(fmaf(v3.y,Ay,By),0.f);
        }
        ax += (v0.x + v1.x) + (v2.x + v3.x);
        ay += (v0.y + v1.y) + (v2.y + v3.y);
    }
    for (; e < end; e++){
        int sI = g_col[e];
        float2 v = h2[sI*32+lane];
        if (MODE){
            v.x = fmaxf(fmaf(v.x,Ax,Bx),0.f);
            v.y = fmaxf(fmaf(v.y,Ay,By),0.f);
        }
        ax += v.x; ay += v.y;
    }
    float2 o; o.x = ax; o.y = ay;
    ((float2*)g_pre)[w*32 + lane] = o;

    __syncthreads();
    if (tid < 64){
        float acc = sPool[0][tid];
        int cur = sGid[0];
        #pragma unroll
        for (int r = 1; r < 8; r++){
            int g = sGid[r];
            if (g != cur){
                atomicAdd(&pooled[cur*64 + tid], acc);
                cur = g; acc = sPool[r][tid];
            } else {
                acc += sPool[r][tid];
            }
        }
        atomicAdd(&pooled[cur*64 + tid], acc);
    }
}

// ---------------- GEMM (100k x 64)@(64 x 64)+bias, FFMA2, fused BN-stats epilogue,
// optional fused BN+relu on the INPUT (coeffs from stats slot) ----------------
template<int APPLY>
__global__ void __launch_bounds__(256) k_gemm(const float* __restrict__ X,
                                              const float* __restrict__ W,
                                              const float* __restrict__ bias,
                                              float* __restrict__ Y,
                                              const float* __restrict__ statsIn,
                                              float* __restrict__ statsOut,
                                              const float* __restrict__ gamma,
                                              const float* __restrict__ beta)
{
    __shared__ float sXT[64][132];
    __shared__ float sW[64][64];
    __shared__ float sA[64], sB[64];
    __shared__ float sSum[64], sSsq[64];
    int tid = threadIdx.x;
    int rowBase = blockIdx.x * 128;
    if (tid < 64){ sSum[tid] = 0.f; sSsq[tid] = 0.f; }
    if (APPLY) bn_coeffs(statsIn, gamma, beta, sA, sB, tid);

    {
        const float4* W4 = (const float4*)W;
        float4* sW4 = (float4*)sW;
        #pragma unroll
        for (int i = 0; i < 4; i++) sW4[tid + i*256] = W4[tid + i*256];
    }
    __syncthreads();

    #pragma unroll
    for (int k = 0; k < 8; k++){
        int l  = tid + k*256;
        int r  = l >> 4;
        int c4 = l & 15;
        int gr = rowBase + r;
        float4 x = make_float4(0.f,0.f,0.f,0.f);
        if (gr < Nn){
            x = ((const float4*)X)[gr*16 + c4];
            if (APPLY){
                float4 A = ((const float4*)sA)[c4];
                float4 B = ((const float4*)sB)[c4];
                x.x = fmaxf(fmaf(x.x,A.x,B.x),0.f);
                x.y = fmaxf(fmaf(x.y,A.y,B.y),0.f);
                x.z = fmaxf(fmaf(x.z,A.z,B.z),0.f);
                x.w = fmaxf(fmaf(x.w,A.w,B.w),0.f);
            }
        }
        int c = c4*4;
        sXT[c+0][r] = x.x; sXT[c+1][r] = x.y; sXT[c+2][r] = x.z; sXT[c+3][r] = x.w;
    }
    __syncthreads();

    int tr = tid >> 4;
    int tc = tid & 15;
    ull acc[4][4];
    #pragma unroll
    for (int i = 0; i < 4; i++)
        #pragma unroll
        for (int j = 0; j < 4; j++) acc[i][j] = 0ULL;

    #pragma unroll 16
    for (int k = 0; k < 64; k++){
        ulonglong2 a01 = *(const ulonglong2*)&sXT[k][tr*8];
        ulonglong2 a23 = *(const ulonglong2*)&sXT[k][tr*8 + 4];
        float4 wv = *(const float4*)&sW[k][tc*4];
        ull w0 = dup2(wv.x), w1 = dup2(wv.y), w2 = dup2(wv.z), w3 = dup2(wv.w);
        fma2(acc[0][0], a01.x, w0); fma2(acc[0][1], a01.x, w1);
        fma2(acc[0][2], a01.x, w2); fma2(acc[0][3], a01.x, w3);
        fma2(acc[1][0], a01.y, w0); fma2(acc[1][1], a01.y, w1);
        fma2(acc[1][2], a01.y, w2); fma2(acc[1][3], a01.y, w3);
        fma2(acc[2][0], a23.x, w0); fma2(acc[2][1], a23.x, w1);
        fma2(acc[2][2], a23.x, w2); fma2(acc[2][3], a23.x, w3);
        fma2(acc[3][0], a23.y, w0); fma2(acc[3][1], a23.y, w1);
        fma2(acc[3][2], a23.y, w2); fma2(acc[3][3], a23.y, w3);
    }

    float4 bi = ((const float4*)bias)[tc];
    float ls[4]  = {0.f,0.f,0.f,0.f};
    float lss[4] = {0.f,0.f,0.f,0.f};
    #pragma unroll
    for (int rp = 0; rp < 4; rp++){
        float2 c0 = u2f2(acc[rp][0]);
        float2 c1 = u2f2(acc[rp][1]);
        float2 c2 = u2f2(acc[rp][2]);
        float2 c3 = u2f2(acc[rp][3]);
        int gr = rowBase + tr*8 + rp*2;
        if (gr < Nn){
            float4 o;
            o.x = c0.x + bi.x; o.y = c1.x + bi.y; o.z = c2.x + bi.z; o.w = c3.x + bi.w;
            *(float4*)&Y[gr*64 + tc*4] = o;
            ls[0] += o.x; ls[1] += o.y; ls[2] += o.z; ls[3] += o.w;
            lss[0] += o.x*o.x; lss[1] += o.y*o.y; lss[2] += o.z*o.z; lss[3] += o.w*o.w;
        }
        if (gr + 1 < Nn){
            float4 o;
            o.x = c0.y + bi.x; o.y = c1.y + bi.y; o.z = c2.y + bi.z; o.w = c3.y + bi.w;
            *(float4*)&Y[(gr+1)*64 + tc*4] = o;
            ls[0] += o.x; ls[1] += o.y; ls[2] += o.z; ls[3] += o.w;
            lss[0] += o.x*o.x; lss[1] += o.y*o.y; lss[2] += o.z*o.z; lss[3] += o.w*o.w;
        }
    }
    #pragma unroll
    for (int c = 0; c < 4; c++){
        ls[c]  += __shfl_xor_sync(0xffffffffu, ls[c],  16);
        lss[c] += __shfl_xor_sync(0xffffffffu, lss[c], 16);
    }
    if ((tid & 31) < 16){
        #pragma unroll
        for (int c = 0; c < 4; c++){
            atomicAdd(&sSum[tc*4+c], ls[c]);
            atomicAdd(&sSsq[tc*4+c], lss[c]);
        }
    }
    __syncthreads();
    if (tid < 64){
        atomicAdd(&statsOut[tid],    sSum[tid]);
        atomicAdd(&statsOut[64+tid], sSsq[tid]);
    }
}

// ---------------- final-layer pooling (BN+relu fused), sorted run-length ----------------
__global__ void k_pool(const float* __restrict__ U, const int* __restrict__ gid,
                       float* __restrict__ pooled,
                       const float* __restrict__ statsIn,
                       const float* __restrict__ gamma,
                       const float* __restrict__ beta)
{
    __shared__ float sA[64], sB[64];
    int tid = threadIdx.x;
    bn_coeffs(statsIn, gamma, beta, sA, sB, tid);
    __syncthreads();
    int col  = tid & 63;
    int rl   = tid >> 6;
    int base = blockIdx.x * 128 + rl*32;
    float a = sA[col], b = sB[col];
    float acc = 0.f; int cur = -1;
    for (int j = 0; j < 32; j++){
        int r = base + j;
        if (r >= Nn) break;
        float x = U[r*64 + col];
        x = fmaxf(fmaf(x, a, b), 0.f);
        int g = gid[r];
        if (g != cur){
            if (cur >= 0) atomicAdd(&pooled[cur*64 + col], acc);
            cur = g; acc = x;
        } else {
            acc += x;
        }
    }
    if (cur >= 0) atomicAdd(&pooled[cur*64 + col], acc);
}

// ---------------- score = sum_i pooled_i @ Wp_i + bp_i ----------------
__global__ void k_score(const float* __restrict__ Wp, const float* __restrict__ bp,
                        float* __restrict__ out)
{
    int t = blockIdx.x*blockDim.x + threadIdx.x;
    if (t >= NG*16) return;
    int g = t >> 4, o = t & 15;
    float acc = 0.f;
    #pragma unroll
    for (int i = 0; i < NPRED; i++){
        const float* __restrict__ P  = &g_pooled[(i*NG + g)*64];
        const float* __restrict__ Wr = Wp + i*64*16 + o;
        float s = 0.f;
        #pragma unroll 16
        for (int k = 0; k < 64; k++) s = fmaf(P[k], Wr[k*16], s);
        acc += s + bp[i*16 + o];
    }
    out[t] = acc;
}

// ---------------- launch ----------------
extern "C" void kernel_launch(void* const* d_in, const int* in_sizes, int n_in,
                              void* d_out, int out_size)
{
    const float* h    = (const float*)d_in[0];
    const int*   esrc = (const int*)  d_in[1];
    const int*   edst = (const int*)  d_in[2];
    const int*   gid  = (const int*)  d_in[3];
    const float* eps  = (const float*)d_in[4];
    const float* W1   = (const float*)d_in[5];
    const float* b1   = (const float*)d_in[6];
    const float* g1   = (const float*)d_in[7];
    const float* be1  = (const float*)d_in[8];
    const float* W2   = (const float*)d_in[9];
    const float* b2   = (const float*)d_in[10];
    const float* g2   = (const float*)d_in[11];
    const float* be2  = (const float*)d_in[12];
    const float* Wp   = (const float*)d_in[13];
    const float* bp   = (const float*)d_in[14];
    float* out = (float*)d_out;

    void *p_pooled, *p_pre, *p_t, *p_u, *p_stats;
    cudaGetSymbolAddress(&p_pooled, g_pooled);
    cudaGetSymbolAddress(&p_pre,    g_pre);
    cudaGetSymbolAddress(&p_t,      g_t);
    cudaGetSymbolAddress(&p_u,      g_u);
    cudaGetSymbolAddress(&p_stats,  g_stats);
    float* stats  = (float*)p_stats;
    float* pooled = (float*)p_pooled;

    // CSR by destination: 3 kernels (hist, chained scan, scatter)
    k_hist<<<(Ee+255)/256, 256>>>(edst);
    k_scan<<<(Nn + 1023)/1024, 1024>>>();
    k_scatter<<<(Ee+255)/256, 256>>>(esrc, edst);

    int gemmB_ = (Nn + 127)/128;
    int aggB   = Nn/8;

    for (int i = 0; i < NGIN; i++){
        float* s1 = stats + (2*i)*128;
        float* s2 = stats + (2*i+1)*128;

        if (i == 0)
            k_agg<0><<<aggB, 256>>>(h, eps, 0, gid, pooled,
                                    nullptr, nullptr, nullptr);
        else
            k_agg<1><<<aggB, 256>>>((const float*)p_u, eps, i, gid,
                                    pooled + (size_t)i*NG*Dd,
                                    stats + (2*(i-1)+1)*128,
                                    g2 + (i-1)*64, be2 + (i-1)*64);

        k_gemm<0><<<gemmB_, 256>>>((const float*)p_pre, W1 + i*4096, b1 + i*64,
                                   (float*)p_t, nullptr, s1, nullptr, nullptr);
        k_gemm<1><<<gemmB_, 256>>>((const float*)p_t, W2 + i*4096, b2 + i*64,
                                   (float*)p_u, s1, s2, g1 + i*64, be1 + i*64);
    }

    k_pool<<<(Nn + 127)/128, 256>>>((const float*)p_u, gid,
                                    pooled + (size_t)NGIN*NG*Dd,
                                    stats + 7*128, g2 + 3*64, be2 + 3*64);

    k_score<<<(NG*16 + 255)/256, 256>>>(Wp, bp, out);
}

// round 6
// speedup vs baseline: 1.2384x; 1.2384x over previous
#include <cuda_runtime.h>

#define Nn 100000
#define Ee 1200000
#define Dd 64
#define NGIN 4
#define NPRED 5
#define NG 512

typedef unsigned long long ull;

__device__ __forceinline__ ull dup2(float x){
    ull r; asm("mov.b64 %0, {%1, %1};" : "=l"(r) : "f"(x)); return r;
}
__device__ __forceinline__ void fma2(ull &d, ull a, ull b){
    asm("fma.rn.f32x2 %0, %1, %2, %0;" : "+l"(d) : "l"(a), "l"(b));
}
__device__ __forceinline__ float2 u2f2(ull v){
    float2 f; asm("mov.b64 {%0, %1}, %2;" : "=f"(f.x), "=f"(f.y) : "l"(v)); return f;
}

// ---------------- scratch ----------------
__device__ float g_pre[Nn*Dd];      // aggregation output
__device__ float g_t[Nn*Dd];        // GEMM1 output
__device__ float g_u[Nn*Dd];        // GEMM2 output (pre-BN)
__device__ int   g_deg[Nn];
__device__ int   g_rowptr[Nn+1];
__device__ int   g_cursor[Nn];
__device__ int   g_col[Ee];         // pre-scaled: src*32 (float2 row offset)
__device__ int   g_bsum[128];
__device__ float g_stats[8*128];    // 8 slots: [0:64) sum, [64:128) sumsq
__device__ float g_pooled[NPRED*NG*Dd];

// ---------------- CSR build (+ fold all zeroing in) ----------------
__global__ void k_hist(const int* __restrict__ dst){
    int i = blockIdx.x*blockDim.x + threadIdx.x;
    if (i < Ee) atomicAdd(&g_deg[dst[i]], 1);
    if (i < NPRED*NG*Dd) g_pooled[i] = 0.f;
    if (i < 8*128) g_stats[i] = 0.f;
}

// scan A: per-block reduce of degree chunk -> g_bsum[b]
__global__ void k_scanA(){
    __shared__ int s[1024];
    int i = blockIdx.x*1024 + threadIdx.x;
    int v = (i < Nn) ? g_deg[i] : 0;
    s[threadIdx.x] = v;
    #pragma unroll
    for (int off = 512; off > 0; off >>= 1){
        __syncthreads();
        if (threadIdx.x < off) s[threadIdx.x] += s[threadIdx.x + off];
    }
    if (threadIdx.x == 0) g_bsum[blockIdx.x] = s[0];
}

// scan B: every block redundantly prefix-scans g_bsum (no cross-block dep),
// then local-scans its chunk and writes rowptr/cursor; self-cleans g_deg.
__global__ void k_scanB(){
    __shared__ int s[1024];
    __shared__ int sb[128];
    int b = blockIdx.x;
    int i = b*1024 + threadIdx.x;

    if (threadIdx.x < 128) sb[threadIdx.x] = (threadIdx.x < 98) ? g_bsum[threadIdx.x] : 0;
    int v = 0;
    if (i < Nn){ v = g_deg[i]; g_deg[i] = 0; }
    s[threadIdx.x] = v;
    __syncthreads();

    // inclusive Hillis-Steele over 128 block sums
    #pragma unroll
    for (int off = 1; off < 128; off <<= 1){
        int x = 0;
        if (threadIdx.x < 128 && threadIdx.x >= off) x = sb[threadIdx.x - off];
        __syncthreads();
        if (threadIdx.x < 128) sb[threadIdx.x] += x;
        __syncthreads();
    }
    // local inclusive scan of the 1024-chunk
    #pragma unroll
    for (int off = 1; off < 1024; off <<= 1){
        int x = (threadIdx.x >= off) ? s[threadIdx.x - off] : 0;
        __syncthreads();
        s[threadIdx.x] += x;
        __syncthreads();
    }
    int excl = (b > 0) ? sb[b-1] : 0;
    if (i < Nn){
        int val = s[threadIdx.x] + excl;
        g_rowptr[i+1] = val;
        if (i+1 < Nn) g_cursor[i+1] = val;
    }
    if (i == 0){ g_rowptr[0] = 0; g_cursor[0] = 0; }
}

__global__ void k_scatter(const int* __restrict__ src, const int* __restrict__ dst){
    int i = blockIdx.x*blockDim.x + threadIdx.x;
    if (i < Ee){
        int p = atomicAdd(&g_cursor[dst[i]], 1);
        g_col[p] = src[i] * 32;      // pre-scaled float2 row offset
    }
}

// ---------------- per-block BN coefficient computation (redundant, cheap) ----------------
__device__ __forceinline__ void bn_coeffs(const float* __restrict__ stats,
                                          const float* __restrict__ gamma,
                                          const float* __restrict__ beta,
                                          float* sA, float* sB, int tid)
{
    if (tid < 64){
        float m = stats[tid]    * (1.f/Nn);
        float v = stats[64+tid] * (1.f/Nn) - m*m;
        float a = gamma[tid] * rsqrtf(v + 1e-5f);
        sA[tid] = a;
        sB[tid] = beta[tid] - m*a;
    }
}

// ---------------- aggregation (warp per node) with fused BN+relu on the source
// AND fused sum-pooling of the BN'd self value (= hidden_rep[layer]) ----------------
template<int MODE>
__global__ void __launch_bounds__(256) k_agg(const float* __restrict__ hin,
                                             const float* __restrict__ eps, int layer,
                                             const int* __restrict__ gid,
                                             float* __restrict__ pooled,
                                             const float* __restrict__ statsIn,
                                             const float* __restrict__ gamma,
                                             const float* __restrict__ beta)
{
    __shared__ float sA[64], sB[64];
    __shared__ float sPool[8][64];
    __shared__ int   sGid[8];
    int tid  = threadIdx.x;
    int wp   = tid >> 5;
    int lane = tid & 31;
    int w    = blockIdx.x*8 + wp;            // node; Nn % 8 == 0 -> always valid

    if (MODE){
        bn_coeffs(statsIn, gamma, beta, sA, sB, tid);
        __syncthreads();
    }

    const float2* __restrict__ h2 = (const float2*)hin;
    float Ax=1.f, Ay=1.f, Bx=0.f, By=0.f;
    if (MODE){
        Ax = sA[2*lane]; Ay = sA[2*lane+1];
        Bx = sB[2*lane]; By = sB[2*lane+1];
    }
    float epv = 1.f + eps[layer];

    float2 s = h2[w*32 + lane];
    float fx = s.x, fy = s.y;
    if (MODE){ fx = fmaxf(fmaf(fx,Ax,Bx),0.f); fy = fmaxf(fmaf(fy,Ay,By),0.f); }
    sPool[wp][2*lane]   = fx;
    sPool[wp][2*lane+1] = fy;
    if (lane == 0) sGid[wp] = gid[w];

    float ax = fx * epv, ay = fy * epv;
    int e = g_rowptr[w], end = g_rowptr[w+1];
    for (; e + 4 <= end; e += 4){
        int o0 = g_col[e], o1 = g_col[e+1], o2 = g_col[e+2], o3 = g_col[e+3];
        float2 v0 = h2[o0+lane], v1 = h2[o1+lane];
        float2 v2 = h2[o2+lane], v3 = h2[o3+lane];
        if (MODE){
            v0.x = fmaxf(fmaf(v0.x,Ax,Bx),0.f); v0.y = fmaxf(fmaf(v0.y,Ay,By),0.f);
            v1.x = fmaxf(fmaf(v1.x,Ax,Bx),0.f); v1.y = fmaxf(fmaf(v1.y,Ay,By),0.f);
            v2.x = fmaxf(fmaf(v2.x,Ax,Bx),0.f); v2.y = fmaxf(fmaf(v2.y,Ay,By),0.f);
            v3.x = fmaxf(fmaf(v3.x,Ax,Bx),0.f); v3.y = fmaxf(fmaf(v3.y,Ay,By),0.f);
        }
        ax += (v0.x + v1.x) + (v2.x + v3.x);
        ay += (v0.y + v1.y) + (v2.y + v3.y);
    }
    for (; e < end; e++){
        int oI = g_col[e];
        float2 v = h2[oI+lane];
        if (MODE){
            v.x = fmaxf(fmaf(v.x,Ax,Bx),0.f);
            v.y = fmaxf(fmaf(v.y,Ay,By),0.f);
        }
        ax += v.x; ay += v.y;
    }
    float2 o; o.x = ax; o.y = ay;
    ((float2*)g_pre)[w*32 + lane] = o;

    __syncthreads();
    if (tid < 64){
        float acc = sPool[0][tid];
        int cur = sGid[0];
        #pragma unroll
        for (int r = 1; r < 8; r++){
            int g = sGid[r];
            if (g != cur){
                atomicAdd(&pooled[cur*64 + tid], acc);
                cur = g; acc = sPool[r][tid];
            } else {
                acc += sPool[r][tid];
            }
        }
        atomicAdd(&pooled[cur*64 + tid], acc);
    }
}

// ---------------- GEMM (100k x 64)@(64 x 64)+bias, FFMA2, fused BN-stats epilogue,
// optional fused BN+relu on the INPUT (coeffs from stats slot) ----------------
template<int APPLY>
__global__ void __launch_bounds__(256) k_gemm(const float* __restrict__ X,
                                              const float* __restrict__ W,
                                              const float* __restrict__ bias,
                                              float* __restrict__ Y,
                                              const float* __restrict__ statsIn,
                                              float* __restrict__ statsOut,
                                              const float* __restrict__ gamma,
                                              const float* __restrict__ beta)
{
    __shared__ float sXT[64][132];
    __shared__ float sW[64][64];
    __shared__ float sA[64], sB[64];
    __shared__ float sSum[64], sSsq[64];
    int tid = threadIdx.x;
    int rowBase = blockIdx.x * 128;
    if (tid < 64){ sSum[tid] = 0.f; sSsq[tid] = 0.f; }
    if (APPLY) bn_coeffs(statsIn, gamma, beta, sA, sB, tid);

    {
        const float4* W4 = (const float4*)W;
        float4* sW4 = (float4*)sW;
        #pragma unroll
        for (int i = 0; i < 4; i++) sW4[tid + i*256] = W4[tid + i*256];
    }
    __syncthreads();

    #pragma unroll
    for (int k = 0; k < 8; k++){
        int l  = tid + k*256;
        int r  = l >> 4;
        int c4 = l & 15;
        int gr = rowBase + r;
        float4 x = make_float4(0.f,0.f,0.f,0.f);
        if (gr < Nn){
            x = ((const float4*)X)[gr*16 + c4];
            if (APPLY){
                float4 A = ((const float4*)sA)[c4];
                float4 B = ((const float4*)sB)[c4];
                x.x = fmaxf(fmaf(x.x,A.x,B.x),0.f);
                x.y = fmaxf(fmaf(x.y,A.y,B.y),0.f);
                x.z = fmaxf(fmaf(x.z,A.z,B.z),0.f);
                x.w = fmaxf(fmaf(x.w,A.w,B.w),0.f);
            }
        }
        int c = c4*4;
        sXT[c+0][r] = x.x; sXT[c+1][r] = x.y; sXT[c+2][r] = x.z; sXT[c+3][r] = x.w;
    }
    __syncthreads();

    int tr = tid >> 4;
    int tc = tid & 15;
    ull acc[4][4];
    #pragma unroll
    for (int i = 0; i < 4; i++)
        #pragma unroll
        for (int j = 0; j < 4; j++) acc[i][j] = 0ULL;

    #pragma unroll 16
    for (int k = 0; k < 64; k++){
        ulonglong2 a01 = *(const ulonglong2*)&sXT[k][tr*8];
        ulonglong2 a23 = *(const ulonglong2*)&sXT[k][tr*8 + 4];
        float4 wv = *(const float4*)&sW[k][tc*4];
        ull w0 = dup2(wv.x), w1 = dup2(wv.y), w2 = dup2(wv.z), w3 = dup2(wv.w);
        fma2(acc[0][0], a01.x, w0); fma2(acc[0][1], a01.x, w1);
        fma2(acc[0][2], a01.x, w2); fma2(acc[0][3], a01.x, w3);
        fma2(acc[1][0], a01.y, w0); fma2(acc[1][1], a01.y, w1);
        fma2(acc[1][2], a01.y, w2); fma2(acc[1][3], a01.y, w3);
        fma2(acc[2][0], a23.x, w0); fma2(acc[2][1], a23.x, w1);
        fma2(acc[2][2], a23.x, w2); fma2(acc[2][3], a23.x, w3);
        fma2(acc[3][0], a23.y, w0); fma2(acc[3][1], a23.y, w1);
        fma2(acc[3][2], a23.y, w2); fma2(acc[3][3], a23.y, w3);
    }

    float4 bi = ((const float4*)bias)[tc];
    float ls[4]  = {0.f,0.f,0.f,0.f};
    float lss[4] = {0.f,0.f,0.f,0.f};
    #pragma unroll
    for (int rp = 0; rp < 4; rp++){
        float2 c0 = u2f2(acc[rp][0]);
        float2 c1 = u2f2(acc[rp][1]);
        float2 c2 = u2f2(acc[rp][2]);
        float2 c3 = u2f2(acc[rp][3]);
        int gr = rowBase + tr*8 + rp*2;
        if (gr < Nn){
            float4 o;
            o.x = c0.x + bi.x; o.y = c1.x + bi.y; o.z = c2.x + bi.z; o.w = c3.x + bi.w;
            *(float4*)&Y[gr*64 + tc*4] = o;
            ls[0] += o.x; ls[1] += o.y; ls[2] += o.z; ls[3] += o.w;
            lss[0] += o.x*o.x; lss[1] += o.y*o.y; lss[2] += o.z*o.z; lss[3] += o.w*o.w;
        }
        if (gr + 1 < Nn){
            float4 o;
            o.x = c0.y + bi.x; o.y = c1.y + bi.y; o.z = c2.y + bi.z; o.w = c3.y + bi.w;
            *(float4*)&Y[(gr+1)*64 + tc*4] = o;
            ls[0] += o.x; ls[1] += o.y; ls[2] += o.z; ls[3] += o.w;
            lss[0] += o.x*o.x; lss[1] += o.y*o.y; lss[2] += o.z*o.z; lss[3] += o.w*o.w;
        }
    }
    #pragma unroll
    for (int c = 0; c < 4; c++){
        ls[c]  += __shfl_xor_sync(0xffffffffu, ls[c],  16);
        lss[c] += __shfl_xor_sync(0xffffffffu, lss[c], 16);
    }
    if ((tid & 31) < 16){
        #pragma unroll
        for (int c = 0; c < 4; c++){
            atomicAdd(&sSum[tc*4+c], ls[c]);
            atomicAdd(&sSsq[tc*4+c], lss[c]);
        }
    }
    __syncthreads();
    if (tid < 64){
        atomicAdd(&statsOut[tid],    sSum[tid]);
        atomicAdd(&statsOut[64+tid], sSsq[tid]);
    }
}

// ---------------- final-layer pooling (BN+relu fused), sorted run-length ----------------
__global__ void k_pool(const float* __restrict__ U, const int* __restrict__ gid,
                       float* __restrict__ pooled,
                       const float* __restrict__ statsIn,
                       const float* __restrict__ gamma,
                       const float* __restrict__ beta)
{
    __shared__ float sA[64], sB[64];
    int tid = threadIdx.x;
    bn_coeffs(statsIn, gamma, beta, sA, sB, tid);
    __syncthreads();
    int col  = tid & 63;
    int rl   = tid >> 6;
    int base = blockIdx.x * 128 + rl*32;
    float a = sA[col], b = sB[col];
    float acc = 0.f; int cur = -1;
    for (int j = 0; j < 32; j++){
        int r = base + j;
        if (r >= Nn) break;
        float x = U[r*64 + col];
        x = fmaxf(fmaf(x, a, b), 0.f);
        int g = gid[r];
        if (g != cur){
            if (cur >= 0) atomicAdd(&pooled[cur*64 + col], acc);
            cur = g; acc = x;
        } else {
            acc += x;
        }
    }
    if (cur >= 0) atomicAdd(&pooled[cur*64 + col], acc);
}

// ---------------- score = sum_i pooled_i @ Wp_i + bp_i ----------------
__global__ void k_score(const float* __restrict__ Wp, const float* __restrict__ bp,
                        float* __restrict__ out)
{
    int t = blockIdx.x*blockDim.x + threadIdx.x;
    if (t >= NG*16) return;
    int g = t >> 4, o = t & 15;
    float acc = 0.f;
    #pragma unroll
    for (int i = 0; i < NPRED; i++){
        const float* __restrict__ P  = &g_pooled[(i*NG + g)*64];
        const float* __restrict__ Wr = Wp + i*64*16 + o;
        float s = 0.f;
        #pragma unroll 16
        for (int k = 0; k < 64; k++) s = fmaf(P[k], Wr[k*16], s);
        acc += s + bp[i*16 + o];
    }
    out[t] = acc;
}

// ---------------- launch ----------------
extern "C" void kernel_launch(void* const* d_in, const int* in_sizes, int n_in,
                              void* d_out, int out_size)
{
    const float* h    = (const float*)d_in[0];
    const int*   esrc = (const int*)  d_in[1];
    const int*   edst = (const int*)  d_in[2];
    const int*   gid  = (const int*)  d_in[3];
    const float* eps  = (const float*)d_in[4];
    const float* W1   = (const float*)d_in[5];
    const float* b1   = (const float*)d_in[6];
    const float* g1   = (const float*)d_in[7];
    const float* be1  = (const float*)d_in[8];
    const float* W2   = (const float*)d_in[9];
    const float* b2   = (const float*)d_in[10];
    const float* g2   = (const float*)d_in[11];
    const float* be2  = (const float*)d_in[12];
    const float* Wp   = (const float*)d_in[13];
    const float* bp   = (const float*)d_in[14];
    float* out = (float*)d_out;

    void *p_pooled, *p_pre, *p_t, *p_u, *p_stats;
    cudaGetSymbolAddress(&p_pooled, g_pooled);
    cudaGetSymbolAddress(&p_pre,    g_pre);
    cudaGetSymbolAddress(&p_t,      g_t);
    cudaGetSymbolAddress(&p_u,      g_u);
    cudaGetSymbolAddress(&p_stats,  g_stats);
    float* stats  = (float*)p_stats;
    float* pooled = (float*)p_pooled;

    // CSR by destination: hist, 2-kernel scan (no cross-block dependencies), scatter
    k_hist<<<(Ee+255)/256, 256>>>(edst);
    int nb = (Nn + 1023)/1024;
    k_scanA<<<nb, 1024>>>();
    k_scanB<<<nb, 1024>>>();
    k_scatter<<<(Ee+255)/256, 256>>>(esrc, edst);

    int gemmB_ = (Nn + 127)/128;
    int aggB   = Nn/8;

    for (int i = 0; i < NGIN; i++){
        float* s1 = stats + (2*i)*128;
        float* s2 = stats + (2*i+1)*128;

        if (i == 0)
            k_agg<0><<<aggB, 256>>>(h, eps, 0, gid, pooled,
                                    nullptr, nullptr, nullptr);
        else
            k_agg<1><<<aggB, 256>>>((const float*)p_u, eps, i, gid,
                                    pooled + (size_t)i*NG*Dd,
                                    stats + (2*(i-1)+1)*128,
                                    g2 + (i-1)*64, be2 + (i-1)*64);

        k_gemm<0><<<gemmB_, 256>>>((const float*)p_pre, W1 + i*4096, b1 + i*64,
                                   (float*)p_t, nullptr, s1, nullptr, nullptr);
        k_gemm<1><<<gemmB_, 256>>>((const float*)p_t, W2 + i*4096, b2 + i*64,
                                   (float*)p_u, s1, s2, g1 + i*64, be1 + i*64);
    }

    k_pool<<<(Nn + 127)/128, 256>>>((const float*)p_u, gid,
                                    pooled + (size_t)NGIN*NG*Dd,
                                    stats + 7*128, g2 + 3*64, be2 + 3*64);

    k_score<<<(NG*16 + 255)/256, 256>>>(Wp, bp, out);
}

// round 8
// speedup vs baseline: 1.2562x; 1.0144x over previous
#include <cuda_runtime.h>
#include <cuda_fp16.h>

#define Nn 100000
#define Ee 1200000
#define Dd 64
#define NGIN 4
#define NPRED 5
#define NG 512

typedef unsigned long long ull;

__device__ __forceinline__ ull dup2(float x){
    ull r; asm("mov.b64 %0, {%1, %1};" : "=l"(r) : "f"(x)); return r;
}
__device__ __forceinline__ void fma2(ull &d, ull a, ull b){
    asm("fma.rn.f32x2 %0, %1, %2, %0;" : "+l"(d) : "l"(a), "l"(b));
}
__device__ __forceinline__ float2 u2f2(ull v){
    float2 f; asm("mov.b64 {%0, %1}, %2;" : "=f"(f.x), "=f"(f.y) : "l"(v)); return f;
}

// ---------------- scratch ----------------
__device__ float g_pre[Nn*Dd];      // aggregation output (fp32)
__device__ float g_t[Nn*Dd];        // GEMM1 output (fp32)
__device__ uint2 g_h16[Nn*16];      // input h converted to half2 (gather source, layer 0)
__device__ uint2 g_u16[Nn*16];      // GEMM2 output in half2 (gather source, layers 1..3 + final pool)
__device__ int   g_deg[Nn];
__device__ int   g_rowptr[Nn+1];
__device__ int   g_rank[Ee];        // within-destination rank of each edge
__device__ int   g_col[Ee];         // pre-scaled: src*32 (half2 row offset)
__device__ int   g_bsum[128];
__device__ float g_stats[8*128];    // 8 slots: [0:64) sum, [64:128) sumsq
__device__ float g_pooled[NPRED*NG*Dd];

// ---------------- CSR hist + rank + h->fp16 conversion + zeroing ----------------
__global__ void k_hist(const int* __restrict__ dst, const float* __restrict__ h){
    int i = blockIdx.x*blockDim.x + threadIdx.x;
    int nthr = gridDim.x*blockDim.x;
    if (i < Ee){
        int r = atomicAdd(&g_deg[dst[i]], 1);
        g_rank[i] = r;
    }
    // convert h (fp32) -> g_h16 (half2 pairs)
    const float4* h4 = (const float4*)h;
    for (int j = i; j < Nn*16; j += nthr){
        float4 x = h4[j];
        __half2 p0 = __float22half2_rn(make_float2(x.x, x.y));
        __half2 p1 = __float22half2_rn(make_float2(x.z, x.w));
        uint2 o;
        o.x = *(unsigned*)&p0;
        o.y = *(unsigned*)&p1;
        g_h16[j] = o;
    }
    if (i < NPRED*NG*Dd) g_pooled[i] = 0.f;
    if (i < 8*128) g_stats[i] = 0.f;
}

// scan A: per-block reduce of degree chunk -> g_bsum[b]
__global__ void k_scanA(){
    __shared__ int s[1024];
    int i = blockIdx.x*1024 + threadIdx.x;
    int v = (i < Nn) ? g_deg[i] : 0;
    s[threadIdx.x] = v;
    #pragma unroll
    for (int off = 512; off > 0; off >>= 1){
        __syncthreads();
        if (threadIdx.x < off) s[threadIdx.x] += s[threadIdx.x + off];
    }
    if (threadIdx.x == 0) g_bsum[blockIdx.x] = s[0];
}

// scan B: every block redundantly prefix-scans g_bsum, then local scan; self-cleans g_deg
__global__ void k_scanB(){
    __shared__ int s[1024];
    __shared__ int sb[128];
    int b = blockIdx.x;
    int i = b*1024 + threadIdx.x;

    if (threadIdx.x < 128) sb[threadIdx.x] = (threadIdx.x < 98) ? g_bsum[threadIdx.x] : 0;
    int v = 0;
    if (i < Nn){ v = g_deg[i]; g_deg[i] = 0; }
    s[threadIdx.x] = v;
    __syncthreads();

    #pragma unroll
    for (int off = 1; off < 128; off <<= 1){
        int x = 0;
        if (threadIdx.x < 128 && threadIdx.x >= off) x = sb[threadIdx.x - off];
        __syncthreads();
        if (threadIdx.x < 128) sb[threadIdx.x] += x;
        __syncthreads();
    }
    #pragma unroll
    for (int off = 1; off < 1024; off <<= 1){
        int x = (threadIdx.x >= off) ? s[threadIdx.x - off] : 0;
        __syncthreads();
        s[threadIdx.x] += x;
        __syncthreads();
    }
    int excl = (b > 0) ? sb[b-1] : 0;
    if (i < Nn){
        int val = s[threadIdx.x] + excl;
        g_rowptr[i+1] = val;
    }
    if (i == 0) g_rowptr[0] = 0;
}

// atomic-free scatter: position = rowptr[dst] + rank
__global__ void k_scatter(const int* __restrict__ src, const int* __restrict__ dst){
    int i = blockIdx.x*blockDim.x + threadIdx.x;
    if (i < Ee){
        int p = g_rowptr[dst[i]] + g_rank[i];
        g_col[p] = src[i] * 32;      // pre-scaled half2 row offset
    }
}

// ---------------- per-block BN coefficient computation ----------------
__device__ __forceinline__ void bn_coeffs(const float* __restrict__ stats,
                                          const float* __restrict__ gamma,
                                          const float* __restrict__ beta,
                                          float* sA, float* sB, int tid)
{
    if (tid < 64){
        float m = stats[tid]    * (1.f/Nn);
        float v = stats[64+tid] * (1.f/Nn) - m*m;
        float a = gamma[tid] * rsqrtf(v + 1e-5f);
        sA[tid] = a;
        sB[tid] = beta[tid] - m*a;
    }
}

// ---------------- aggregation (warp per node), fp16 gather source,
// fused BN+relu + fused sum-pooling of the BN'd self value ----------------
template<int MODE>
__global__ void __launch_bounds__(256) k_agg(const uint2* __restrict__ hsrc,
                                             const float* __restrict__ eps, int layer,
                                             const int* __restrict__ gid,
                                             float* __restrict__ pooled,
                                             const float* __restrict__ statsIn,
                                             const float* __restrict__ gamma,
                                             const float* __restrict__ beta)
{
    __shared__ float sA[64], sB[64];
    __shared__ float sPool[8][64];
    __shared__ int   sGid[8];
    int tid  = threadIdx.x;
    int wp   = tid >> 5;
    int lane = tid & 31;
    int w    = blockIdx.x*8 + wp;

    if (MODE){
        bn_coeffs(statsIn, gamma, beta, sA, sB, tid);
        __syncthreads();
    }

    const __half2* __restrict__ hh = (const __half2*)hsrc;
    float Ax=1.f, Ay=1.f, Bx=0.f, By=0.f;
    if (MODE){
        Ax = sA[2*lane]; Ay = sA[2*lane+1];
        Bx = sB[2*lane]; By = sB[2*lane+1];
    }
    float epv = 1.f + eps[layer];

    float2 s = __half22float2(hh[w*32 + lane]);
    float fx = s.x, fy = s.y;
    if (MODE){ fx = fmaxf(fmaf(fx,Ax,Bx),0.f); fy = fmaxf(fmaf(fy,Ay,By),0.f); }
    sPool[wp][2*lane]   = fx;
    sPool[wp][2*lane+1] = fy;
    if (lane == 0) sGid[wp] = gid[w];

    float ax = fx * epv, ay = fy * epv;
    int e = g_rowptr[w], end = g_rowptr[w+1];
    for (; e + 4 <= end; e += 4){
        int o0 = g_col[e], o1 = g_col[e+1], o2 = g_col[e+2], o3 = g_col[e+3];
        float2 v0 = __half22float2(hh[o0+lane]);
        float2 v1 = __half22float2(hh[o1+lane]);
        float2 v2 = __half22float2(hh[o2+lane]);
        float2 v3 = __half22float2(hh[o3+lane]);
        if (MODE){
            v0.x = fmaxf(fmaf(v0.x,Ax,Bx),0.f); v0.y = fmaxf(fmaf(v0.y,Ay,By),0.f);
            v1.x = fmaxf(fmaf(v1.x,Ax,Bx),0.f); v1.y = fmaxf(fmaf(v1.y,Ay,By),0.f);
            v2.x = fmaxf(fmaf(v2.x,Ax,Bx),0.f); v2.y = fmaxf(fmaf(v2.y,Ay,By),0.f);
            v3.x = fmaxf(fmaf(v3.x,Ax,Bx),0.f); v3.y = fmaxf(fmaf(v3.y,Ay,By),0.f);
        }
        ax += (v0.x + v1.x) + (v2.x + v3.x);
        ay += (v0.y + v1.y) + (v2.y + v3.y);
    }
    for (; e < end; e++){
        int oI = g_col[e];
        float2 v = __half22float2(hh[oI+lane]);
        if (MODE){
            v.x = fmaxf(fmaf(v.x,Ax,Bx),0.f);
            v.y = fmaxf(fmaf(v.y,Ay,By),0.f);
        }
        ax += v.x; ay += v.y;
    }
    float2 o; o.x = ax; o.y = ay;
    ((float2*)g_pre)[w*32 + lane] = o;

    __syncthreads();
    if (tid < 64){
        float acc = sPool[0][tid];
        int cur = sGid[0];
        #pragma unroll
        for (int r = 1; r < 8; r++){
            int g = sGid[r];
            if (g != cur){
                atomicAdd(&pooled[cur*64 + tid], acc);
                cur = g; acc = sPool[r][tid];
            } else {
                acc += sPool[r][tid];
            }
        }
        atomicAdd(&pooled[cur*64 + tid], acc);
    }
}

// ---------------- GEMM (100k x 64)@(64 x 64)+bias, FFMA2, fused BN-stats epilogue,
// optional fused BN+relu on the INPUT; output fp32 or fp16 ----------------
template<int APPLY, int OUT16>
__global__ void __launch_bounds__(256) k_gemm(const float* __restrict__ X,
                                              const float* __restrict__ W,
                                              const float* __restrict__ bias,
                                              void* __restrict__ Yv,
                                              const float* __restrict__ statsIn,
                                              float* __restrict__ statsOut,
                                              const float* __restrict__ gamma,
                                              const float* __restrict__ beta)
{
    __shared__ float sXT[64][132];
    __shared__ float sW[64][64];
    __shared__ float sA[64], sB[64];
    __shared__ float sSum[64], sSsq[64];
    int tid = threadIdx.x;
    int rowBase = blockIdx.x * 128;
    if (tid < 64){ sSum[tid] = 0.f; sSsq[tid] = 0.f; }
    if (APPLY) bn_coeffs(statsIn, gamma, beta, sA, sB, tid);

    {
        const float4* W4 = (const float4*)W;
        float4* sW4 = (float4*)sW;
        #pragma unroll
        for (int i = 0; i < 4; i++) sW4[tid + i*256] = W4[tid + i*256];
    }
    __syncthreads();

    #pragma unroll
    for (int k = 0; k < 8; k++){
        int l  = tid + k*256;
        int r  = l >> 4;
        int c4 = l & 15;
        int gr = rowBase + r;
        float4 x = make_float4(0.f,0.f,0.f,0.f);
        if (gr < Nn){
            x = ((const float4*)X)[gr*16 + c4];
            if (APPLY){
                float4 A = ((const float4*)sA)[c4];
                float4 B = ((const float4*)sB)[c4];
                x.x = fmaxf(fmaf(x.x,A.x,B.x),0.f);
                x.y = fmaxf(fmaf(x.y,A.y,B.y),0.f);
                x.z = fmaxf(fmaf(x.z,A.z,B.z),0.f);
                x.w = fmaxf(fmaf(x.w,A.w,B.w),0.f);
            }
        }
        int c = c4*4;
        sXT[c+0][r] = x.x; sXT[c+1][r] = x.y; sXT[c+2][r] = x.z; sXT[c+3][r] = x.w;
    }
    __syncthreads();

    int tr = tid >> 4;
    int tc = tid & 15;
    ull acc[4][4];
    #pragma unroll
    for (int i = 0; i < 4; i++)
        #pragma unroll
        for (int j = 0; j < 4; j++) acc[i][j] = 0ULL;

    #pragma unroll 16
    for (int k = 0; k < 64; k++){
        ulonglong2 a01 = *(const ulonglong2*)&sXT[k][tr*8];
        ulonglong2 a23 = *(const ulonglong2*)&sXT[k][tr*8 + 4];
        float4 wv = *(const float4*)&sW[k][tc*4];
        ull w0 = dup2(wv.x), w1 = dup2(wv.y), w2 = dup2(wv.z), w3 = dup2(wv.w);
        fma2(acc[0][0], a01.x, w0); fma2(acc[0][1], a01.x, w1);
        fma2(acc[0][2], a01.x, w2); fma2(acc[0][3], a01.x, w3);
        fma2(acc[1][0], a01.y, w0); fma2(acc[1][1], a01.y, w1);
        fma2(acc[1][2], a01.y, w2); fma2(acc[1][3], a01.y, w3);
        fma2(acc[2][0], a23.x, w0); fma2(acc[2][1], a23.x, w1);
        fma2(acc[2][2], a23.x, w2); fma2(acc[2][3], a23.x, w3);
        fma2(acc[3][0], a23.y, w0); fma2(acc[3][1], a23.y, w1);
        fma2(acc[3][2], a23.y, w2); fma2(acc[3][3], a23.y, w3);
    }

    float4 bi = ((const float4*)bias)[tc];
    float ls[4]  = {0.f,0.f,0.f,0.f};
    float lss[4] = {0.f,0.f,0.f,0.f};
    #pragma unroll
    for (int rp = 0; rp < 4; rp++){
        float2 c0 = u2f2(acc[rp][0]);
        float2 c1 = u2f2(acc[rp][1]);
        float2 c2 = u2f2(acc[rp][2]);
        float2 c3 = u2f2(acc[rp][3]);
        #pragma unroll
        for (int half = 0; half < 2; half++){
            int gr = rowBase + tr*8 + rp*2 + half;
            if (gr < Nn){
                float4 o;
                if (half == 0){
                    o.x = c0.x + bi.x; o.y = c1.x + bi.y; o.z = c2.x + bi.z; o.w = c3.x + bi.w;
                } else {
                    o.x = c0.y + bi.x; o.y = c1.y + bi.y; o.z = c2.y + bi.z; o.w = c3.y + bi.w;
                }
                if (OUT16){
                    __half2 p0 = __float22half2_rn(make_float2(o.x, o.y));
                    __half2 p1 = __float22half2_rn(make_float2(o.z, o.w));
                    uint2 st; st.x = *(unsigned*)&p0; st.y = *(unsigned*)&p1;
                    ((uint2*)Yv)[gr*16 + tc] = st;
                } else {
                    *(float4*)&((float*)Yv)[gr*64 + tc*4] = o;
                }
                ls[0] += o.x; ls[1] += o.y; ls[2] += o.z; ls[3] += o.w;
                lss[0] += o.x*o.x; lss[1] += o.y*o.y; lss[2] += o.z*o.z; lss[3] += o.w*o.w;
            }
        }
    }
    #pragma unroll
    for (int c = 0; c < 4; c++){
        ls[c]  += __shfl_xor_sync(0xffffffffu, ls[c],  16);
        lss[c] += __shfl_xor_sync(0xffffffffu, lss[c], 16);
    }
    if ((tid & 31) < 16){
        #pragma unroll
        for (int c = 0; c < 4; c++){
            atomicAdd(&sSum[tc*4+c], ls[c]);
            atomicAdd(&sSsq[tc*4+c], lss[c]);
        }
    }
    __syncthreads();
    if (tid < 64){
        atomicAdd(&statsOut[tid],    sSum[tid]);
        atomicAdd(&statsOut[64+tid], sSsq[tid]);
    }
}

// ---------------- final-layer pooling (BN+relu fused), fp16 source ----------------
__global__ void k_pool(const uint2* __restrict__ U16, const int* __restrict__ gid,
                       float* __restrict__ pooled,
                       const float* __restrict__ statsIn,
                       const float* __restrict__ gamma,
                       const float* __restrict__ beta)
{
    __shared__ float sA[64], sB[64];
    int tid = threadIdx.x;
    bn_coeffs(statsIn, gamma, beta, sA, sB, tid);
    __syncthreads();
    const __half* __restrict__ Uh = (const __half*)U16;
    int col  = tid & 63;
    int rl   = tid >> 6;
    int base = blockIdx.x * 128 + rl*32;
    float a = sA[col], b = sB[col];
    float acc = 0.f; int cur = -1;
    for (int j = 0; j < 32; j++){
        int r = base + j;
        if (r >= Nn) break;
        float x = __half2float(Uh[r*64 + col]);
        x = fmaxf(fmaf(x, a, b), 0.f);
        int g = gid[r];
        if (g != cur){
            if (cur >= 0) atomicAdd(&pooled[cur*64 + col], acc);
            cur = g; acc = x;
        } else {
            acc += x;
        }
    }
    if (cur >= 0) atomicAdd(&pooled[cur*64 + col], acc);
}

// ---------------- score = sum_i pooled_i @ Wp_i + bp_i ----------------
__global__ void k_score(const float* __restrict__ Wp, const float* __restrict__ bp,
                        float* __restrict__ out)
{
    int t = blockIdx.x*blockDim.x + threadIdx.x;
    if (t >= NG*16) return;
    int g = t >> 4, o = t & 15;
    float acc = 0.f;
    #pragma unroll
    for (int i = 0; i < NPRED; i++){
        const float* __restrict__ P  = &g_pooled[(i*NG + g)*64];
        const float* __restrict__ Wr = Wp + i*64*16 + o;
        float s = 0.f;
        #pragma unroll 16
        for (int k = 0; k < 64; k++) s = fmaf(P[k], Wr[k*16], s);
        acc += s + bp[i*16 + o];
    }
    out[t] = acc;
}

// ---------------- launch ----------------
extern "C" void kernel_launch(void* const* d_in, const int* in_sizes, int n_in,
                              void* d_out, int out_size)
{
    const float* h    = (const float*)d_in[0];
    const int*   esrc = (const int*)  d_in[1];
    const int*   edst = (const int*)  d_in[2];
    const int*   gid  = (const int*)  d_in[3];
    const float* eps  = (const float*)d_in[4];
    const float* W1   = (const float*)d_in[5];
    const float* b1   = (const float*)d_in[6];
    const float* g1   = (const float*)d_in[7];
    const float* be1  = (const float*)d_in[8];
    const float* W2   = (const float*)d_in[9];
    const float* b2   = (const float*)d_in[10];
    const float* g2   = (const float*)d_in[11];
    const float* be2  = (const float*)d_in[12];
    const float* Wp   = (const float*)d_in[13];
    const float* bp   = (const float*)d_in[14];
    float* out = (float*)d_out;

    void *p_pooled, *p_pre, *p_t, *p_u16, *p_h16, *p_stats;
    cudaGetSymbolAddress(&p_pooled, g_pooled);
    cudaGetSymbolAddress(&p_pre,    g_pre);
    cudaGetSymbolAddress(&p_t,      g_t);
    cudaGetSymbolAddress(&p_u16,    g_u16);
    cudaGetSymbolAddress(&p_h16,    g_h16);
    cudaGetSymbolAddress(&p_stats,  g_stats);
    float* stats  = (float*)p_stats;
    float* pooled = (float*)p_pooled;

    // CSR by destination: hist(+rank+convert), 2-kernel scan, atomic-free scatter
    k_hist<<<(Ee+255)/256, 256>>>(edst, h);
    int nb = (Nn + 1023)/1024;
    k_scanA<<<nb, 1024>>>();
    k_scanB<<<nb, 1024>>>();
    k_scatter<<<(Ee+255)/256, 256>>>(esrc, edst);

    int gemmB_ = (Nn + 127)/128;
    int aggB   = Nn/8;

    for (int i = 0; i < NGIN; i++){
        float* s1 = stats + (2*i)*128;
        float* s2 = stats + (2*i+1)*128;

        if (i == 0)
            k_agg<0><<<aggB, 256>>>((const uint2*)p_h16, eps, 0, gid, pooled,
                                    nullptr, nullptr, nullptr);
        else
            k_agg<1><<<aggB, 256>>>((const uint2*)p_u16, eps, i, gid,
                                    pooled + (size_t)i*NG*Dd,
                                    stats + (2*(i-1)+1)*128,
                                    g2 + (i-1)*64, be2 + (i-1)*64);

        k_gemm<0,0><<<gemmB_, 256>>>((const float*)p_pre, W1 + i*4096, b1 + i*64,
                                     p_t, nullptr, s1, nullptr, nullptr);
        k_gemm<1,1><<<gemmB_, 256>>>((const float*)p_t, W2 + i*4096, b2 + i*64,
                                     p_u16, s1, s2, g1 + i*64, be1 + i*64);
    }

    k_pool<<<(Nn + 127)/128, 256>>>((const uint2*)p_u16, gid,
                                    pooled + (size_t)NGIN*NG*Dd,
                                    stats + 7*128, g2 + 3*64, be2 + 3*64);

    k_score<<<(NG*16 + 255)/256, 256>>>(Wp, bp, out);
}

// round 11
// speedup vs baseline: 1.5856x; 1.2622x over previous
#include <cuda_runtime.h>
#include <cuda_fp16.h>

#define Nn 100000
#define Ee 1200000
#define Dd 64
#define NGIN 4
#define NPRED 5
#define NG 512

// SW128 swizzle on byte offsets (bits [6:4] ^= bits [9:7])
#define SW(b) ((b) ^ (((b) >> 3) & 0x70))

__device__ __forceinline__ unsigned sptr(const void* p){
    return (unsigned)__cvta_generic_to_shared(p);
}
__device__ __forceinline__ void ldm_x4(unsigned addr, unsigned &r0, unsigned &r1,
                                       unsigned &r2, unsigned &r3){
    asm volatile("ldmatrix.sync.aligned.m8n8.x4.shared.b16 {%0,%1,%2,%3}, [%4];"
        : "=r"(r0),"=r"(r1),"=r"(r2),"=r"(r3) : "r"(addr));
}
__device__ __forceinline__ void ldm_x4t(unsigned addr, unsigned &r0, unsigned &r1,
                                        unsigned &r2, unsigned &r3){
    asm volatile("ldmatrix.sync.aligned.m8n8.x4.trans.shared.b16 {%0,%1,%2,%3}, [%4];"
        : "=r"(r0),"=r"(r1),"=r"(r2),"=r"(r3) : "r"(addr));
}
__device__ __forceinline__ void mma16816(float* d, const unsigned* a, unsigned b0, unsigned b1){
    asm volatile("mma.sync.aligned.m16n8k16.row.col.f32.f16.f16.f32 "
        "{%0,%1,%2,%3}, {%4,%5,%6,%7}, {%8,%9}, {%0,%1,%2,%3};"
        : "+f"(d[0]),"+f"(d[1]),"+f"(d[2]),"+f"(d[3])
        : "r"(a[0]),"r"(a[1]),"r"(a[2]),"r"(a[3]),"r"(b0),"r"(b1));
}

// ---------------- scratch ----------------
__device__ uint2 g_h16[Nn*16];      // input h as half2 (gather source, layer 0): 128 B/row
__device__ uint4 g_pre16[Nn*8];     // agg output, fp16 (GEMM1 input): 128 B/row
__device__ uint4 g_t16[Nn*8];       // GEMM1 output, fp16 (GEMM2 input, pre-BN)
__device__ uint4 g_u16[Nn*8];       // GEMM2 output, fp16 (gather source next layer / final pool)
__device__ int   g_deg[Nn];
__device__ int   g_rowptr[Nn+1];
__device__ int   g_rank[Ee];        // within-destination rank of each edge
__device__ int   g_col[Ee];         // pre-scaled: src*32 (half2 row offset)
__device__ int   g_bsum[128];
__device__ float g_stats[8*128];    // 8 slots: [0:64) sum, [64:128) sumsq
__device__ float g_pooled[NPRED*NG*Dd];

// ---------------- CSR hist + rank + h->fp16 conversion + zeroing ----------------
__global__ void k_hist(const int* __restrict__ dst, const float* __restrict__ h){
    int i = blockIdx.x*blockDim.x + threadIdx.x;
    int nthr = gridDim.x*blockDim.x;
    if (i < Ee){
        int r = atomicAdd(&g_deg[dst[i]], 1);
        g_rank[i] = r;
    }
    const float4* h4 = (const float4*)h;
    for (int j = i; j < Nn*16; j += nthr){
        float4 x = h4[j];
        __half2 p0 = __float22half2_rn(make_float2(x.x, x.y));
        __half2 p1 = __float22half2_rn(make_float2(x.z, x.w));
        uint2 o;
        o.x = *(unsigned*)&p0;
        o.y = *(unsigned*)&p1;
        g_h16[j] = o;
    }
    if (i < NPRED*NG*Dd) g_pooled[i] = 0.f;
    if (i < 8*128) g_stats[i] = 0.f;
}

// scan A: per-block reduce of degree chunk -> g_bsum[b]
__global__ void k_scanA(){
    __shared__ int s[1024];
    int i = blockIdx.x*1024 + threadIdx.x;
    int v = (i < Nn) ? g_deg[i] : 0;
    s[threadIdx.x] = v;
    #pragma unroll
    for (int off = 512; off > 0; off >>= 1){
        __syncthreads();
        if (threadIdx.x < off) s[threadIdx.x] += s[threadIdx.x + off];
    }
    if (threadIdx.x == 0) g_bsum[blockIdx.x] = s[0];
}

// scan B: every block redundantly prefix-scans g_bsum, then local scan; self-cleans g_deg
__global__ void k_scanB(){
    __shared__ int s[1024];
    __shared__ int sb[128];
    int b = blockIdx.x;
    int i = b*1024 + threadIdx.x;

    if (threadIdx.x < 128) sb[threadIdx.x] = (threadIdx.x < 98) ? g_bsum[threadIdx.x] : 0;
    int v = 0;
    if (i < Nn){ v = g_deg[i]; g_deg[i] = 0; }
    s[threadIdx.x] = v;
    __syncthreads();

    #pragma unroll
    for (int off = 1; off < 128; off <<= 1){
        int x = 0;
        if (threadIdx.x < 128 && threadIdx.x >= off) x = sb[threadIdx.x - off];
        __syncthreads();
        if (threadIdx.x < 128) sb[threadIdx.x] += x;
        __syncthreads();
    }
    #pragma unroll
    for (int off = 1; off < 1024; off <<= 1){
        int x = (threadIdx.x >= off) ? s[threadIdx.x - off] : 0;
        __syncthreads();
        s[threadIdx.x] += x;
        __syncthreads();
    }
    int excl = (b > 0) ? sb[b-1] : 0;
    if (i < Nn){
        int val = s[threadIdx.x] + excl;
        g_rowptr[i+1] = val;
    }
    if (i == 0) g_rowptr[0] = 0;
}

// atomic-free scatter: position = rowptr[dst] + rank
__global__ void k_scatter(const int* __restrict__ src, const int* __restrict__ dst){
    int i = blockIdx.x*blockDim.x + threadIdx.x;
    if (i < Ee){
        int p = g_rowptr[dst[i]] + g_rank[i];
        g_col[p] = src[i] * 32;      // pre-scaled half2 row offset
    }
}

// ---------------- per-block BN coefficient computation ----------------
__device__ __forceinline__ void bn_coeffs(const float* __restrict__ stats,
                                          const float* __restrict__ gamma,
                                          const float* __restrict__ beta,
                                          float* sA, float* sB, int tid)
{
    if (tid < 64){
        float m = stats[tid]    * (1.f/Nn);
        float v = stats[64+tid] * (1.f/Nn) - m*m;
        float a = gamma[tid] * rsqrtf(v + 1e-5f);
        sA[tid] = a;
        sB[tid] = beta[tid] - m*a;
    }
}

// ---------------- aggregation (warp per node), fp16 gather source,
// fused BN+relu + fused sum-pooling; output fp16 (GEMM1 input) ----------------
template<int MODE>
__global__ void __launch_bounds__(256) k_agg(const __half2* __restrict__ hh,
                                             const float* __restrict__ eps, int layer,
                                             const int* __restrict__ gid,
                                             float* __restrict__ pooled,
                                             const float* __restrict__ statsIn,
                                             const float* __restrict__ gamma,
                                             const float* __restrict__ beta)
{
    __shared__ float sA[64], sB[64];
    __shared__ float sPool[8][64];
    __shared__ int   sGid[8];
    int tid  = threadIdx.x;
    int wp   = tid >> 5;
    int lane = tid & 31;
    int w    = blockIdx.x*8 + wp;

    if (MODE){
        bn_coeffs(statsIn, gamma, beta, sA, sB, tid);
        __syncthreads();
    }

    float Ax=1.f, Ay=1.f, Bx=0.f, By=0.f;
    if (MODE){
        Ax = sA[2*lane]; Ay = sA[2*lane+1];
        Bx = sB[2*lane]; By = sB[2*lane+1];
    }
    float epv = 1.f + eps[layer];

    float2 s = __half22float2(hh[w*32 + lane]);
    float fx = s.x, fy = s.y;
    if (MODE){ fx = fmaxf(fmaf(fx,Ax,Bx),0.f); fy = fmaxf(fmaf(fy,Ay,By),0.f); }
    sPool[wp][2*lane]   = fx;
    sPool[wp][2*lane+1] = fy;
    if (lane == 0) sGid[wp] = gid[w];

    float ax = fx * epv, ay = fy * epv;
    int e = g_rowptr[w], end = g_rowptr[w+1];
    for (; e + 4 <= end; e += 4){
        int o0 = g_col[e], o1 = g_col[e+1], o2 = g_col[e+2], o3 = g_col[e+3];
        float2 v0 = __half22float2(hh[o0+lane]);
        float2 v1 = __half22float2(hh[o1+lane]);
        float2 v2 = __half22float2(hh[o2+lane]);
        float2 v3 = __half22float2(hh[o3+lane]);
        if (MODE){
            v0.x = fmaxf(fmaf(v0.x,Ax,Bx),0.f); v0.y = fmaxf(fmaf(v0.y,Ay,By),0.f);
            v1.x = fmaxf(fmaf(v1.x,Ax,Bx),0.f); v1.y = fmaxf(fmaf(v1.y,Ay,By),0.f);
            v2.x = fmaxf(fmaf(v2.x,Ax,Bx),0.f); v2.y = fmaxf(fmaf(v2.y,Ay,By),0.f);
            v3.x = fmaxf(fmaf(v3.x,Ax,Bx),0.f); v3.y = fmaxf(fmaf(v3.y,Ay,By),0.f);
        }
        ax += (v0.x + v1.x) + (v2.x + v3.x);
        ay += (v0.y + v1.y) + (v2.y + v3.y);
    }
    for (; e < end; e++){
        int oI = g_col[e];
        float2 v = __half22float2(hh[oI+lane]);
        if (MODE){
            v.x = fmaxf(fmaf(v.x,Ax,Bx),0.f);
            v.y = fmaxf(fmaf(v.y,Ay,By),0.f);
        }
        ax += v.x; ay += v.y;
    }
    __half2 hv = __float22half2_rn(make_float2(ax, ay));
    ((__half2*)g_pre16)[w*32 + lane] = hv;

    __syncthreads();
    if (tid < 64){
        float acc = sPool[0][tid];
        int cur = sGid[0];
        #pragma unroll
        for (int r = 1; r < 8; r++){
            int g = sGid[r];
            if (g != cur){
                atomicAdd(&pooled[cur*64 + tid], acc);
                cur = g; acc = sPool[r][tid];
            } else {
                acc += sPool[r][tid];
            }
        }
        atomicAdd(&pooled[cur*64 + tid], acc);
    }
}

// ---------------- HMMA GEMM: (256 rows/block x 64) @ (64 x 64) + bias, fp16 in / fp16 out,
// fp32 accumulate, fused BN-stats; optional fused BN+relu on INPUT ----------------
template<int APPLY>
__global__ void __launch_bounds__(256, 2) k_gemm(const uint4* __restrict__ X16,
                                                 const float* __restrict__ W,
                                                 const float* __restrict__ bias,
                                                 unsigned* __restrict__ Y,   // half2 units
                                                 const float* __restrict__ statsIn,
                                                 float* __restrict__ statsOut,
                                                 const float* __restrict__ gamma,
                                                 const float* __restrict__ beta)
{
    __shared__ uint4 sX4[256*8];     // 256 rows x 64 halfs, SW128 swizzled (16B-aligned)
    __shared__ uint4 sW4[64*8];      // 64 k-rows x 64 halfs (fp16), SW128 swizzled
    __shared__ float sA[64], sB[64], sBias[64];
    __shared__ float sSum[64], sSsq[64];
    char* sX  = (char*)sX4;
    char* sWt = (char*)sW4;
    int tid = threadIdx.x;
    int rowBase = blockIdx.x * 256;
    if (tid < 64){ sSum[tid] = 0.f; sSsq[tid] = 0.f; sBias[tid] = bias[tid]; }
    if (APPLY) bn_coeffs(statsIn, gamma, beta, sA, sB, tid);

    // load W fp32 -> fp16 smem (half2 granularity)
    {
        const float2* W2 = (const float2*)W;
        #pragma unroll
        for (int it = 0; it < 8; it++){
            int idx = tid + it*256;          // 0..2047 half2 units
            int k  = idx >> 5;               // k row
            int n2 = idx & 31;               // half2 col
            __half2 hw = __float22half2_rn(W2[idx]);
            *(unsigned*)(sWt + SW(k*128 + n2*4)) = *(unsigned*)&hw;
        }
    }
    __syncthreads();   // sA/sB ready for X loader

    // load X (fp16 global) -> swizzled smem, optional BN+relu
    #pragma unroll
    for (int it = 0; it < 8; it++){
        int idx = tid + it*256;              // 0..2047 uint4 (16B = 8 halfs)
        int r = idx >> 3;
        int c = idx & 7;
        int gr = rowBase + r;
        uint4 v = make_uint4(0,0,0,0);
        if (gr < Nn){
            v = X16[gr*8 + c];
            if (APPLY){
                __half2* ph = (__half2*)&v;
                #pragma unroll
                for (int q = 0; q < 4; q++){
                    float2 f = __half22float2(ph[q]);
                    int col = c*8 + q*2;
                    f.x = fmaxf(fmaf(f.x, sA[col],   sB[col]),   0.f);
                    f.y = fmaxf(fmaf(f.y, sA[col+1], sB[col+1]), 0.f);
                    ph[q] = __float22half2_rn(f);
                }
            }
        }
        *(uint4*)(sX + SW(r*128 + c*16)) = v;
    }
    __syncthreads();

    int wid  = tid >> 5;
    int lane = tid & 31;
    int warpRow = wid * 32;
    unsigned sXb = sptr(sX);
    unsigned sWb = sptr(sWt);

    float acc[2][8][4];
    #pragma unroll
    for (int mt = 0; mt < 2; mt++)
        #pragma unroll
        for (int nt = 0; nt < 8; nt++)
            #pragma unroll
            for (int q = 0; q < 4; q++) acc[mt][nt][q] = 0.f;

    int sel = lane >> 3;          // ldmatrix sub-matrix selector
    int lr  = lane & 7;
    #pragma unroll
    for (int ks = 0; ks < 4; ks++){
        unsigned a[2][4];
        #pragma unroll
        for (int mt = 0; mt < 2; mt++){
            int rowl = warpRow + mt*16 + lr + ((sel & 1) << 3);
            int kb   = ks*32 + ((sel >> 1) << 4);
            ldm_x4(sXb + SW(rowl*128 + kb), a[mt][0], a[mt][1], a[mt][2], a[mt][3]);
        }
        #pragma unroll
        for (int j = 0; j < 4; j++){
            int kr = ks*16 + lr + ((sel & 1) << 3);
            int nb = j*32 + ((sel >> 1) << 4);
            unsigned b0, b1, b2, b3;
            ldm_x4t(sWb + SW(kr*128 + nb), b0, b1, b2, b3);
            mma16816(acc[0][2*j],   a[0], b0, b1);
            mma16816(acc[1][2*j],   a[1], b0, b1);
            mma16816(acc[0][2*j+1], a[0], b2, b3);
            mma16816(acc[1][2*j+1], a[1], b2, b3);
        }
    }

    // epilogue: bias, fp16 store, BN-stats (shuffle reduce -> smem atomics)
    int g  = lane >> 2;
    int i4 = lane & 3;
    int i2 = i4 * 2;
    #pragma unroll
    for (int nt = 0; nt < 8; nt++){
        float b0f = sBias[nt*8 + i2];
        float b1f = sBias[nt*8 + i2 + 1];
        float s0 = 0.f, s1 = 0.f, q0 = 0.f, q1 = 0.f;
        #pragma unroll
        for (int mt = 0; mt < 2; mt++){
            int row0 = rowBase + warpRow + mt*16 + g;
            float d0 = acc[mt][nt][0] + b0f;
            float d1 = acc[mt][nt][1] + b1f;
            float d2 = acc[mt][nt][2] + b0f;
            float d3 = acc[mt][nt][3] + b1f;
            if (row0 < Nn){
                __half2 hv = __float22half2_rn(make_float2(d0, d1));
                Y[row0*32 + nt*4 + i4] = *(unsigned*)&hv;
                s0 += d0; s1 += d1; q0 += d0*d0; q1 += d1*d1;
            }
            if (row0 + 8 < Nn){
                __half2 hv = __float22half2_rn(make_float2(d2, d3));
                Y[(row0+8)*32 + nt*4 + i4] = *(unsigned*)&hv;
                s0 += d2; s1 += d3; q0 += d2*d2; q1 += d3*d3;
            }
        }
        #pragma unroll
        for (int off = 4; off < 32; off <<= 1){
            s0 += __shfl_xor_sync(0xffffffffu, s0, off);
            s1 += __shfl_xor_sync(0xffffffffu, s1, off);
            q0 += __shfl_xor_sync(0xffffffffu, q0, off);
            q1 += __shfl_xor_sync(0xffffffffu, q1, off);
        }
        if (lane < 4){
            atomicAdd(&sSum[nt*8 + lane*2],     s0);
            atomicAdd(&sSum[nt*8 + lane*2 + 1], s1);
            atomicAdd(&sSsq[nt*8 + lane*2],     q0);
            atomicAdd(&sSsq[nt*8 + lane*2 + 1], q1);
        }
    }
    __syncthreads();
    if (tid < 64){
        atomicAdd(&statsOut[tid],    sSum[tid]);
        atomicAdd(&statsOut[64+tid], sSsq[tid]);
    }
}

// ---------------- final-layer pooling (BN+relu fused), fp16 source ----------------
__global__ void k_pool(const __half* __restrict__ Uh, const int* __restrict__ gid,
                       float* __restrict__ pooled,
                       const float* __restrict__ statsIn,
                       const float* __restrict__ gamma,
                       const float* __restrict__ beta)
{
    __shared__ float sA[64], sB[64];
    int tid = threadIdx.x;
    bn_coeffs(statsIn, gamma, beta, sA, sB, tid);
    __syncthreads();
    int col  = tid & 63;
    int rl   = tid >> 6;
    int base = blockIdx.x * 128 + rl*32;
    float a = sA[col], b = sB[col];
    float acc = 0.f; int cur = -1;
    for (int j = 0; j < 32; j++){
        int r = base + j;
        if (r >= Nn) break;
        float x = __half2float(Uh[r*64 + col]);
        x = fmaxf(fmaf(x, a, b), 0.f);
        int g = gid[r];
        if (g != cur){
            if (cur >= 0) atomicAdd(&pooled[cur*64 + col], acc);
            cur = g; acc = x;
        } else {
            acc += x;
        }
    }
    if (cur >= 0) atomicAdd(&pooled[cur*64 + col], acc);
}

// ---------------- score = sum_i pooled_i @ Wp_i + bp_i ----------------
__global__ void k_score(const float* __restrict__ Wp, const float* __restrict__ bp,
                        float* __restrict__ out)
{
    int t = blockIdx.x*blockDim.x + threadIdx.x;
    if (t >= NG*16) return;
    int g = t >> 4, o = t & 15;
    float acc = 0.f;
    #pragma unroll
    for (int i = 0; i < NPRED; i++){
        const float* __restrict__ P  = &g_pooled[(i*NG + g)*64];
        const float* __restrict__ Wr = Wp + i*64*16 + o;
        float s = 0.f;
        #pragma unroll 16
        for (int k = 0; k < 64; k++) s = fmaf(P[k], Wr[k*16], s);
        acc += s + bp[i*16 + o];
    }
    out[t] = acc;
}

// ---------------- launch ----------------
extern "C" void kernel_launch(void* const* d_in, const int* in_sizes, int n_in,
                              void* d_out, int out_size)
{
    const float* h    = (const float*)d_in[0];
    const int*   esrc = (const int*)  d_in[1];
    const int*   edst = (const int*)  d_in[2];
    const int*   gid  = (const int*)  d_in[3];
    const float* eps  = (const float*)d_in[4];
    const float* W1   = (const float*)d_in[5];
    const float* b1   = (const float*)d_in[6];
    const float* g1   = (const float*)d_in[7];
    const float* be1  = (const float*)d_in[8];
    const float* W2   = (const float*)d_in[9];
    const float* b2   = (const float*)d_in[10];
    const float* g2   = (const float*)d_in[11];
    const float* be2  = (const float*)d_in[12];
    const float* Wp   = (const float*)d_in[13];
    const float* bp   = (const float*)d_in[14];
    float* out = (float*)d_out;

    void *p_pooled, *p_pre16, *p_t16, *p_u16, *p_h16, *p_stats;
    cudaGetSymbolAddress(&p_pooled, g_pooled);
    cudaGetSymbolAddress(&p_pre16,  g_pre16);
    cudaGetSymbolAddress(&p_t16,    g_t16);
    cudaGetSymbolAddress(&p_u16,    g_u16);
    cudaGetSymbolAddress(&p_h16,    g_h16);
    cudaGetSymbolAddress(&p_stats,  g_stats);
    float* stats  = (float*)p_stats;
    float* pooled = (float*)p_pooled;

    // CSR by destination: hist(+rank+convert), 2-kernel scan, atomic-free scatter
    k_hist<<<(Ee+255)/256, 256>>>(edst, h);
    int nb = (Nn + 1023)/1024;
    k_scanA<<<nb, 1024>>>();
    k_scanB<<<nb, 1024>>>();
    k_scatter<<<(Ee+255)/256, 256>>>(esrc, edst);

    int gemmB_ = (Nn + 255)/256;
    int aggB   = Nn/8;

    for (int i = 0; i < NGIN; i++){
        float* s1 = stats + (2*i)*128;
        float* s2 = stats + (2*i+1)*128;

        if (i == 0)
            k_agg<0><<<aggB, 256>>>((const __half2*)p_h16, eps, 0, gid, pooled,
                                    nullptr, nullptr, nullptr);
        else
            k_agg<1><<<aggB, 256>>>((const __half2*)p_u16, eps, i, gid,
                                    pooled + (size_t)i*NG*Dd,
                                    stats + (2*(i-1)+1)*128,
                                    g2 + (i-1)*64, be2 + (i-1)*64);

        k_gemm<0><<<gemmB_, 256>>>((const uint4*)p_pre16, W1 + i*4096, b1 + i*64,
                                   (unsigned*)p_t16, nullptr, s1, nullptr, nullptr);
        k_gemm<1><<<gemmB_, 256>>>((const uint4*)p_t16, W2 + i*4096, b2 + i*64,
                                   (unsigned*)p_u16, s1, s2, g1 + i*64, be1 + i*64);
    }

    k_pool<<<(Nn + 127)/128, 256>>>((const __half*)p_u16, gid,
                                    pooled + (size_t)NGIN*NG*Dd,
                                    stats + 7*128, g2 + 3*64, be2 + 3*64);

    k_score<<<(NG*16 + 255)/256, 256>>>(Wp, bp, out);
}

// round 12
// speedup vs baseline: 1.5975x; 1.0075x over previous
#include <cuda_runtime.h>
#include <cuda_fp16.h>

#define Nn 100000
#define Ee 1200000
#define Dd 64
#define NGIN 4
#define NPRED 5
#define NG 512

// SW128 swizzle on byte offsets (bits [6:4] ^= bits [9:7])
#define SW(b) ((b) ^ (((b) >> 3) & 0x70))

__device__ __forceinline__ unsigned sptr(const void* p){
    return (unsigned)__cvta_generic_to_shared(p);
}
__device__ __forceinline__ void ldm_x4(unsigned addr, unsigned &r0, unsigned &r1,
                                       unsigned &r2, unsigned &r3){
    asm volatile("ldmatrix.sync.aligned.m8n8.x4.shared.b16 {%0,%1,%2,%3}, [%4];"
        : "=r"(r0),"=r"(r1),"=r"(r2),"=r"(r3) : "r"(addr));
}
__device__ __forceinline__ void ldm_x4t(unsigned addr, unsigned &r0, unsigned &r1,
                                        unsigned &r2, unsigned &r3){
    asm volatile("ldmatrix.sync.aligned.m8n8.x4.trans.shared.b16 {%0,%1,%2,%3}, [%4];"
        : "=r"(r0),"=r"(r1),"=r"(r2),"=r"(r3) : "r"(addr));
}
__device__ __forceinline__ void mma16816(float* d, const unsigned* a, unsigned b0, unsigned b1){
    asm volatile("mma.sync.aligned.m16n8k16.row.col.f32.f16.f16.f32 "
        "{%0,%1,%2,%3}, {%4,%5,%6,%7}, {%8,%9}, {%0,%1,%2,%3};"
        : "+f"(d[0]),"+f"(d[1]),"+f"(d[2]),"+f"(d[3])
        : "r"(a[0]),"r"(a[1]),"r"(a[2]),"r"(a[3]),"r"(b0),"r"(b1));
}

// ---------------- scratch ----------------
__device__ uint2 g_h16[Nn*16];      // input h as half2 (gather source, layer 0): 128 B/row
__device__ uint4 g_pre16[Nn*8];     // agg output, fp16 (GEMM1 input): 128 B/row
__device__ uint4 g_t16[Nn*8];       // GEMM1 output, fp16 (GEMM2 input, pre-BN)
__device__ uint4 g_u16[Nn*8];       // GEMM2 output, fp16 (gather source next layer / final pool)
__device__ int   g_deg[Nn];
__device__ int   g_rowptr[Nn+1];
__device__ int   g_rank[Ee];        // within-destination rank of each edge
__device__ int   g_col[Ee];         // pre-scaled: src*32 (half2 row offset)
__device__ int   g_bsum[128];
__device__ float g_stats[8*128];    // 8 slots: [0:64) sum, [64:128) sumsq
__device__ float g_pooled[NPRED*NG*Dd];

// ---------------- CSR hist + rank + h->fp16 conversion + zeroing ----------------
__global__ void k_hist(const int* __restrict__ dst, const float* __restrict__ h){
    int i = blockIdx.x*blockDim.x + threadIdx.x;
    int nthr = gridDim.x*blockDim.x;
    if (i < Ee){
        int r = atomicAdd(&g_deg[dst[i]], 1);
        g_rank[i] = r;
    }
    const float4* h4 = (const float4*)h;
    for (int j = i; j < Nn*16; j += nthr){
        float4 x = h4[j];
        __half2 p0 = __float22half2_rn(make_float2(x.x, x.y));
        __half2 p1 = __float22half2_rn(make_float2(x.z, x.w));
        uint2 o;
        o.x = *(unsigned*)&p0;
        o.y = *(unsigned*)&p1;
        g_h16[j] = o;
    }
    if (i < NPRED*NG*Dd) g_pooled[i] = 0.f;
    if (i < 8*128) g_stats[i] = 0.f;
}

// scan A: per-block reduce of degree chunk -> g_bsum[b]
__global__ void k_scanA(){
    __shared__ int s[1024];
    int i = blockIdx.x*1024 + threadIdx.x;
    int v = (i < Nn) ? g_deg[i] : 0;
    s[threadIdx.x] = v;
    #pragma unroll
    for (int off = 512; off > 0; off >>= 1){
        __syncthreads();
        if (threadIdx.x < off) s[threadIdx.x] += s[threadIdx.x + off];
    }
    if (threadIdx.x == 0) g_bsum[blockIdx.x] = s[0];
}

// scan B: every block redundantly prefix-scans g_bsum, then local scan; self-cleans g_deg
__global__ void k_scanB(){
    __shared__ int s[1024];
    __shared__ int sb[128];
    int b = blockIdx.x;
    int i = b*1024 + threadIdx.x;

    if (threadIdx.x < 128) sb[threadIdx.x] = (threadIdx.x < 98) ? g_bsum[threadIdx.x] : 0;
    int v = 0;
    if (i < Nn){ v = g_deg[i]; g_deg[i] = 0; }
    s[threadIdx.x] = v;
    __syncthreads();

    #pragma unroll
    for (int off = 1; off < 128; off <<= 1){
        int x = 0;
        if (threadIdx.x < 128 && threadIdx.x >= off) x = sb[threadIdx.x - off];
        __syncthreads();
        if (threadIdx.x < 128) sb[threadIdx.x] += x;
        __syncthreads();
    }
    #pragma unroll
    for (int off = 1; off < 1024; off <<= 1){
        int x = (threadIdx.x >= off) ? s[threadIdx.x - off] : 0;
        __syncthreads();
        s[threadIdx.x] += x;
        __syncthreads();
    }
    int excl = (b > 0) ? sb[b-1] : 0;
    if (i < Nn){
        int val = s[threadIdx.x] + excl;
        g_rowptr[i+1] = val;
    }
    if (i == 0) g_rowptr[0] = 0;
}

// atomic-free scatter: position = rowptr[dst] + rank
__global__ void k_scatter(const int* __restrict__ src, const int* __restrict__ dst){
    int i = blockIdx.x*blockDim.x + threadIdx.x;
    if (i < Ee){
        int p = g_rowptr[dst[i]] + g_rank[i];
        g_col[p] = src[i] * 32;      // pre-scaled half2 row offset
    }
}

// ---------------- per-block BN coefficient computation ----------------
__device__ __forceinline__ void bn_coeffs(const float* __restrict__ stats,
                                          const float* __restrict__ gamma,
                                          const float* __restrict__ beta,
                                          float* sA, float* sB, int tid)
{
    if (tid < 64){
        float m = stats[tid]    * (1.f/Nn);
        float v = stats[64+tid] * (1.f/Nn) - m*m;
        float a = gamma[tid] * rsqrtf(v + 1e-5f);
        sA[tid] = a;
        sB[tid] = beta[tid] - m*a;
    }
}

// ---------------- aggregation (warp per node), fp16 gather source,
// software-pipelined col prefetch, half2 BN+relu, fused pooling ----------------
template<int MODE>
__global__ void __launch_bounds__(256) k_agg(const __half2* __restrict__ hh,
                                             const float* __restrict__ eps, int layer,
                                             const int* __restrict__ gid,
                                             float* __restrict__ pooled,
                                             const float* __restrict__ statsIn,
                                             const float* __restrict__ gamma,
                                             const float* __restrict__ beta)
{
    __shared__ float sA[64], sB[64];
    __shared__ float sPool[8][64];
    __shared__ int   sGid[8];
    int tid  = threadIdx.x;
    int wp   = tid >> 5;
    int lane = tid & 31;
    int w    = blockIdx.x*8 + wp;

    if (MODE){
        bn_coeffs(statsIn, gamma, beta, sA, sB, tid);
        __syncthreads();
    }

    __half2 A2 = __float2half2_rn(1.f), B2 = __float2half2_rn(0.f);
    const __half2 Z2 = __float2half2_rn(0.f);
    float Ax=1.f, Ay=1.f, Bx=0.f, By=0.f;
    if (MODE){
        Ax = sA[2*lane]; Ay = sA[2*lane+1];
        Bx = sB[2*lane]; By = sB[2*lane+1];
        A2 = __floats2half2_rn(Ax, Ay);
        B2 = __floats2half2_rn(Bx, By);
    }
    float epv = 1.f + eps[layer];

    float2 s = __half22float2(hh[w*32 + lane]);
    float fx = s.x, fy = s.y;
    if (MODE){ fx = fmaxf(fmaf(fx,Ax,Bx),0.f); fy = fmaxf(fmaf(fy,Ay,By),0.f); }
    sPool[wp][2*lane]   = fx;
    sPool[wp][2*lane+1] = fy;
    if (lane == 0) sGid[wp] = gid[w];

    float ax = fx * epv, ay = fy * epv;
    int e = g_rowptr[w], end = g_rowptr[w+1];

    // pipelined 4-edge chunks: prefetch next chunk's cols before gathering current
    int o0=0, o1=0, o2=0, o3=0;
    bool have = (e + 4 <= end);
    if (have){ o0 = g_col[e]; o1 = g_col[e+1]; o2 = g_col[e+2]; o3 = g_col[e+3]; }
    while (have){
        int p0=0, p1=0, p2=0, p3=0;
        bool nxt = (e + 8 <= end);
        if (nxt){ p0 = g_col[e+4]; p1 = g_col[e+5]; p2 = g_col[e+6]; p3 = g_col[e+7]; }
        __half2 v0 = hh[o0+lane];
        __half2 v1 = hh[o1+lane];
        __half2 v2 = hh[o2+lane];
        __half2 v3 = hh[o3+lane];
        if (MODE){
            v0 = __hmax2(__hfma2(v0, A2, B2), Z2);
            v1 = __hmax2(__hfma2(v1, A2, B2), Z2);
            v2 = __hmax2(__hfma2(v2, A2, B2), Z2);
            v3 = __hmax2(__hfma2(v3, A2, B2), Z2);
        }
        float2 f0 = __half22float2(v0);
        float2 f1 = __half22float2(v1);
        float2 f2 = __half22float2(v2);
        float2 f3 = __half22float2(v3);
        ax += (f0.x + f1.x) + (f2.x + f3.x);
        ay += (f0.y + f1.y) + (f2.y + f3.y);
        o0 = p0; o1 = p1; o2 = p2; o3 = p3;
        e += 4;
        have = nxt;
    }
    for (; e < end; e++){
        __half2 v = hh[g_col[e] + lane];
        if (MODE) v = __hmax2(__hfma2(v, A2, B2), Z2);
        float2 f = __half22float2(v);
        ax += f.x; ay += f.y;
    }

    __half2 hv = __float22half2_rn(make_float2(ax, ay));
    ((__half2*)g_pre16)[w*32 + lane] = hv;

    __syncthreads();
    if (tid < 64){
        float acc = sPool[0][tid];
        int cur = sGid[0];
        #pragma unroll
        for (int r = 1; r < 8; r++){
            int g = sGid[r];
            if (g != cur){
                atomicAdd(&pooled[cur*64 + tid], acc);
                cur = g; acc = sPool[r][tid];
            } else {
                acc += sPool[r][tid];
            }
        }
        atomicAdd(&pooled[cur*64 + tid], acc);
    }
}

// ---------------- HMMA GEMM: (256 rows/block x 64) @ (64 x 64) + bias, fp16 in / fp16 out,
// fp32 accumulate, fused BN-stats; optional fused BN+relu on INPUT ----------------
template<int APPLY>
__global__ void __launch_bounds__(256, 2) k_gemm(const uint4* __restrict__ X16,
                                                 const float* __restrict__ W,
                                                 const float* __restrict__ bias,
                                                 unsigned* __restrict__ Y,   // half2 units
                                                 const float* __restrict__ statsIn,
                                                 float* __restrict__ statsOut,
                                                 const float* __restrict__ gamma,
                                                 const float* __restrict__ beta)
{
    __shared__ uint4 sX4[256*8];     // 256 rows x 64 halfs, SW128 swizzled (16B-aligned)
    __shared__ uint4 sW4[64*8];      // 64 k-rows x 64 halfs (fp16), SW128 swizzled
    __shared__ float sA[64], sB[64], sBias[64];
    __shared__ float sSum[64], sSsq[64];
    char* sX  = (char*)sX4;
    char* sWt = (char*)sW4;
    int tid = threadIdx.x;
    int rowBase = blockIdx.x * 256;
    if (tid < 64){ sSum[tid] = 0.f; sSsq[tid] = 0.f; sBias[tid] = bias[tid]; }
    if (APPLY) bn_coeffs(statsIn, gamma, beta, sA, sB, tid);

    // load W fp32 -> fp16 smem (half2 granularity)
    {
        const float2* W2 = (const float2*)W;
        #pragma unroll
        for (int it = 0; it < 8; it++){
            int idx = tid + it*256;          // 0..2047 half2 units
            int k  = idx >> 5;               // k row
            int n2 = idx & 31;               // half2 col
            __half2 hw = __float22half2_rn(W2[idx]);
            *(unsigned*)(sWt + SW(k*128 + n2*4)) = *(unsigned*)&hw;
        }
    }
    __syncthreads();   // sA/sB ready for X loader

    // load X (fp16 global) -> swizzled smem, optional BN+relu
    #pragma unroll
    for (int it = 0; it < 8; it++){
        int idx = tid + it*256;              // 0..2047 uint4 (16B = 8 halfs)
        int r = idx >> 3;
        int c = idx & 7;
        int gr = rowBase + r;
        uint4 v = make_uint4(0,0,0,0);
        if (gr < Nn){
            v = X16[gr*8 + c];
            if (APPLY){
                __half2* ph = (__half2*)&v;
                #pragma unroll
                for (int q = 0; q < 4; q++){
                    float2 f = __half22float2(ph[q]);
                    int col = c*8 + q*2;
                    f.x = fmaxf(fmaf(f.x, sA[col],   sB[col]),   0.f);
                    f.y = fmaxf(fmaf(f.y, sA[col+1], sB[col+1]), 0.f);
                    ph[q] = __float22half2_rn(f);
                }
            }
        }
        *(uint4*)(sX + SW(r*128 + c*16)) = v;
    }
    __syncthreads();

    int wid  = tid >> 5;
    int lane = tid & 31;
    int warpRow = wid * 32;
    unsigned sXb = sptr(sX);
    unsigned sWb = sptr(sWt);

    float acc[2][8][4];
    #pragma unroll
    for (int mt = 0; mt < 2; mt++)
        #pragma unroll
        for (int nt = 0; nt < 8; nt++)
            #pragma unroll
            for (int q = 0; q < 4; q++) acc[mt][nt][q] = 0.f;

    int sel = lane >> 3;          // ldmatrix sub-matrix selector
    int lr  = lane & 7;
    #pragma unroll
    for (int ks = 0; ks < 4; ks++){
        unsigned a[2][4];
        #pragma unroll
        for (int mt = 0; mt < 2; mt++){
            int rowl = warpRow + mt*16 + lr + ((sel & 1) << 3);
            int kb   = ks*32 + ((sel >> 1) << 4);
            ldm_x4(sXb + SW(rowl*128 + kb), a[mt][0], a[mt][1], a[mt][2], a[mt][3]);
        }
        #pragma unroll
        for (int j = 0; j < 4; j++){
            int kr = ks*16 + lr + ((sel & 1) << 3);
            int nb = j*32 + ((sel >> 1) << 4);
            unsigned b0, b1, b2, b3;
            ldm_x4t(sWb + SW(kr*128 + nb), b0, b1, b2, b3);
            mma16816(acc[0][2*j],   a[0], b0, b1);
            mma16816(acc[1][2*j],   a[1], b0, b1);
            mma16816(acc[0][2*j+1], a[0], b2, b3);
            mma16816(acc[1][2*j+1], a[1], b2, b3);
        }
    }

    // epilogue: bias, fp16 store, BN-stats (shuffle reduce -> smem atomics)
    int g  = lane >> 2;
    int i4 = lane & 3;
    int i2 = i4 * 2;
    #pragma unroll
    for (int nt = 0; nt < 8; nt++){
        float b0f = sBias[nt*8 + i2];
        float b1f = sBias[nt*8 + i2 + 1];
        float s0 = 0.f, s1 = 0.f, q0 = 0.f, q1 = 0.f;
        #pragma unroll
        for (int mt = 0; mt < 2; mt++){
            int row0 = rowBase + warpRow + mt*16 + g;
            float d0 = acc[mt][nt][0] + b0f;
            float d1 = acc[mt][nt][1] + b1f;
            float d2 = acc[mt][nt][2] + b0f;
            float d3 = acc[mt][nt][3] + b1f;
            if (row0 < Nn){
                __half2 hv = __float22half2_rn(make_float2(d0, d1));
                Y[row0*32 + nt*4 + i4] = *(unsigned*)&hv;
                s0 += d0; s1 += d1; q0 += d0*d0; q1 += d1*d1;
            }
            if (row0 + 8 < Nn){
                __half2 hv = __float22half2_rn(make_float2(d2, d3));
                Y[(row0+8)*32 + nt*4 + i4] = *(unsigned*)&hv;
                s0 += d2; s1 += d3; q0 += d2*d2; q1 += d3*d3;
            }
        }
        #pragma unroll
        for (int off = 4; off < 32; off <<= 1){
            s0 += __shfl_xor_sync(0xffffffffu, s0, off);
            s1 += __shfl_xor_sync(0xffffffffu, s1, off);
            q0 += __shfl_xor_sync(0xffffffffu, q0, off);
            q1 += __shfl_xor_sync(0xffffffffu, q1, off);
        }
        if (lane < 4){
            atomicAdd(&sSum[nt*8 + lane*2],     s0);
            atomicAdd(&sSum[nt*8 + lane*2 + 1], s1);
            atomicAdd(&sSsq[nt*8 + lane*2],     q0);
            atomicAdd(&sSsq[nt*8 + lane*2 + 1], q1);
        }
    }
    __syncthreads();
    if (tid < 64){
        atomicAdd(&statsOut[tid],    sSum[tid]);
        atomicAdd(&statsOut[64+tid], sSsq[tid]);
    }
}

// ---------------- final-layer pooling (BN+relu fused), fp16 source ----------------
__global__ void k_pool(const __half* __restrict__ Uh, const int* __restrict__ gid,
                       float* __restrict__ pooled,
                       const float* __restrict__ statsIn,
                       const float* __restrict__ gamma,
                       const float* __restrict__ beta)
{
    __shared__ float sA[64], sB[64];
    int tid = threadIdx.x;
    bn_coeffs(statsIn, gamma, beta, sA, sB, tid);
    __syncthreads();
    int col  = tid & 63;
    int rl   = tid >> 6;
    int base = blockIdx.x * 128 + rl*32;
    float a = sA[col], b = sB[col];
    float acc = 0.f; int cur = -1;
    for (int j = 0; j < 32; j++){
        int r = base + j;
        if (r >= Nn) break;
        float x = __half2float(Uh[r*64 + col]);
        x = fmaxf(fmaf(x, a, b), 0.f);
        int g = gid[r];
        if (g != cur){
            if (cur >= 0) atomicAdd(&pooled[cur*64 + col], acc);
            cur = g; acc = x;
        } else {
            acc += x;
        }
    }
    if (cur >= 0) atomicAdd(&pooled[cur*64 + col], acc);
}

// ---------------- score = sum_i pooled_i @ Wp_i + bp_i ----------------
__global__ void k_score(const float* __restrict__ Wp, const float* __restrict__ bp,
                        float* __restrict__ out)
{
    int t = blockIdx.x*blockDim.x + threadIdx.x;
    if (t >= NG*16) return;
    int g = t >> 4, o = t & 15;
    float acc = 0.f;
    #pragma unroll
    for (int i = 0; i < NPRED; i++){
        const float* __restrict__ P  = &g_pooled[(i*NG + g)*64];
        const float* __restrict__ Wr = Wp + i*64*16 + o;
        float s = 0.f;
        #pragma unroll 16
        for (int k = 0; k < 64; k++) s = fmaf(P[k], Wr[k*16], s);
        acc += s + bp[i*16 + o];
    }
    out[t] = acc;
}

// ---------------- launch ----------------
extern "C" void kernel_launch(void* const* d_in, const int* in_sizes, int n_in,
                              void* d_out, int out_size)
{
    const float* h    = (const float*)d_in[0];
    const int*   esrc = (const int*)  d_in[1];
    const int*   edst = (const int*)  d_in[2];
    const int*   gid  = (const int*)  d_in[3];
    const float* eps  = (const float*)d_in[4];
    const float* W1   = (const float*)d_in[5];
    const float* b1   = (const float*)d_in[6];
    const float* g1   = (const float*)d_in[7];
    const float* be1  = (const float*)d_in[8];
    const float* W2   = (const float*)d_in[9];
    const float* b2   = (const float*)d_in[10];
    const float* g2   = (const float*)d_in[11];
    const float* be2  = (const float*)d_in[12];
    const float* Wp   = (const float*)d_in[13];
    const float* bp   = (const float*)d_in[14];
    float* out = (float*)d_out;

    void *p_pooled, *p_pre16, *p_t16, *p_u16, *p_h16, *p_stats;
    cudaGetSymbolAddress(&p_pooled, g_pooled);
    cudaGetSymbolAddress(&p_pre16,  g_pre16);
    cudaGetSymbolAddress(&p_t16,    g_t16);
    cudaGetSymbolAddress(&p_u16,    g_u16);
    cudaGetSymbolAddress(&p_h16,    g_h16);
    cudaGetSymbolAddress(&p_stats,  g_stats);
    float* stats  = (float*)p_stats;
    float* pooled = (float*)p_pooled;

    // CSR by destination: hist(+rank+convert), 2-kernel scan, atomic-free scatter
    k_hist<<<(Ee+255)/256, 256>>>(edst, h);
    int nb = (Nn + 1023)/1024;
    k_scanA<<<nb, 1024>>>();
    k_scanB<<<nb, 1024>>>();
    k_scatter<<<(Ee+255)/256, 256>>>(esrc, edst);

    int gemmB_ = (Nn + 255)/256;
    int aggB   = Nn/8;

    for (int i = 0; i < NGIN; i++){
        float* s1 = stats + (2*i)*128;
        float* s2 = stats + (2*i+1)*128;

        if (i == 0)
            k_agg<0><<<aggB, 256>>>((const __half2*)p_h16, eps, 0, gid, pooled,
                                    nullptr, nullptr, nullptr);
        else
            k_agg<1><<<aggB, 256>>>((const __half2*)p_u16, eps, i, gid,
                                    pooled + (size_t)i*NG*Dd,
                                    stats + (2*(i-1)+1)*128,
                                    g2 + (i-1)*64, be2 + (i-1)*64);

        k_gemm<0><<<gemmB_, 256>>>((const uint4*)p_pre16, W1 + i*4096, b1 + i*64,
                                   (unsigned*)p_t16, nullptr, s1, nullptr, nullptr);
        k_gemm<1><<<gemmB_, 256>>>((const uint4*)p_t16, W2 + i*4096, b2 + i*64,
                                   (unsigned*)p_u16, s1, s2, g1 + i*64, be1 + i*64);
    }

    k_pool<<<(Nn + 127)/128, 256>>>((const __half*)p_u16, gid,
                                    pooled + (size_t)NGIN*NG*Dd,
                                    stats + 7*128, g2 + 3*64, be2 + 3*64);

    k_score<<<(NG*16 + 255)/256, 256>>>(Wp, bp, out);
}

// round 13
// speedup vs baseline: 1.6858x; 1.0553x over previous
#include <cuda_runtime.h>
#include <cuda_fp16.h>

#define Nn 100000
#define Ee 1200000
#define Dd 64
#define NGIN 4
#define NPRED 5
#define NG 512

// SW128 swizzle on byte offsets (bits [6:4] ^= bits [9:7])
#define SW(b) ((b) ^ (((b) >> 3) & 0x70))

__device__ __forceinline__ unsigned sptr(const void* p){
    return (unsigned)__cvta_generic_to_shared(p);
}
__device__ __forceinline__ void ldm_x4(unsigned addr, unsigned &r0, unsigned &r1,
                                       unsigned &r2, unsigned &r3){
    asm volatile("ldmatrix.sync.aligned.m8n8.x4.shared.b16 {%0,%1,%2,%3}, [%4];"
        : "=r"(r0),"=r"(r1),"=r"(r2),"=r"(r3) : "r"(addr));
}
__device__ __forceinline__ void ldm_x4t(unsigned addr, unsigned &r0, unsigned &r1,
                                        unsigned &r2, unsigned &r3){
    asm volatile("ldmatrix.sync.aligned.m8n8.x4.trans.shared.b16 {%0,%1,%2,%3}, [%4];"
        : "=r"(r0),"=r"(r1),"=r"(r2),"=r"(r3) : "r"(addr));
}
__device__ __forceinline__ void mma16816(float* d, const unsigned* a, unsigned b0, unsigned b1){
    asm volatile("mma.sync.aligned.m16n8k16.row.col.f32.f16.f16.f32 "
        "{%0,%1,%2,%3}, {%4,%5,%6,%7}, {%8,%9}, {%0,%1,%2,%3};"
        : "+f"(d[0]),"+f"(d[1]),"+f"(d[2]),"+f"(d[3])
        : "r"(a[0]),"r"(a[1]),"r"(a[2]),"r"(a[3]),"r"(b0),"r"(b1));
}

// ---------------- scratch ----------------
__device__ uint2 g_h16[Nn*16];      // input h as half2 (gather source, layer 0): 128 B/row
__device__ uint4 g_pre16[Nn*8];     // agg output, fp16 (GEMM1 input): 128 B/row
__device__ uint4 g_t16[Nn*8];       // GEMM1 output, fp16 (GEMM2 input, pre-BN)
__device__ uint4 g_u16[Nn*8];       // GEMM2 output, fp16 (gather source next layer / final pool)
__device__ int   g_deg[Nn];
__device__ int   g_rowptr[Nn+1];
__device__ int   g_rank[Ee];        // within-destination rank of each edge
__device__ int   g_col[Ee];         // pre-scaled: src*16 (uint2 row offset)
__device__ int   g_bsum[128];
__device__ int   g_scanCount;       // grid-barrier counter (reset in k_hist)
__device__ float g_stats[8*128];    // 8 slots: [0:64) sum, [64:128) sumsq
__device__ float g_pooled[NPRED*NG*Dd];

// ---------------- CSR hist + rank + h->fp16 conversion + zeroing ----------------
__global__ void k_hist(const int* __restrict__ dst, const float* __restrict__ h){
    int i = blockIdx.x*blockDim.x + threadIdx.x;
    int nthr = gridDim.x*blockDim.x;
    if (i < Ee){
        int r = atomicAdd(&g_deg[dst[i]], 1);
        g_rank[i] = r;
    }
    const float4* h4 = (const float4*)h;
    for (int j = i; j < Nn*16; j += nthr){
        float4 x = h4[j];
        __half2 p0 = __float22half2_rn(make_float2(x.x, x.y));
        __half2 p1 = __float22half2_rn(make_float2(x.z, x.w));
        uint2 o;
        o.x = *(unsigned*)&p0;
        o.y = *(unsigned*)&p1;
        g_h16[j] = o;
    }
    if (i < NPRED*NG*Dd) g_pooled[i] = 0.f;
    if (i < 8*128) g_stats[i] = 0.f;
    if (i == 0) g_scanCount = 0;
}

// single-kernel scan: phase 1 local scan + bsum, resident-grid barrier, phase 2 prefix.
// grid = 98 blocks x 1024 (all resident on 148 SMs -> spin is deadlock-free)
__global__ void k_scan(int nb){
    __shared__ int s[1024];
    __shared__ int sb[128];
    int b = blockIdx.x;
    int i = b*1024 + threadIdx.x;
    int v = 0;
    if (i < Nn){ v = g_deg[i]; g_deg[i] = 0; }   // self-clean for next replay
    s[threadIdx.x] = v;
    __syncthreads();
    #pragma unroll
    for (int off = 1; off < 1024; off <<= 1){
        int x = (threadIdx.x >= off) ? s[threadIdx.x - off] : 0;
        __syncthreads();
        s[threadIdx.x] += x;
        __syncthreads();
    }
    if (threadIdx.x == 1023){
        g_bsum[b] = s[1023];
        __threadfence();
    }
    __syncthreads();
    if (threadIdx.x == 0){
        atomicAdd(&g_scanCount, 1);
        while (atomicAdd(&g_scanCount, 0) < nb) { }
        __threadfence();
    }
    __syncthreads();

    if (threadIdx.x < 128) sb[threadIdx.x] = (threadIdx.x < nb) ? g_bsum[threadIdx.x] : 0;
    __syncthreads();
    #pragma unroll
    for (int off = 1; off < 128; off <<= 1){
        int x = 0;
        if (threadIdx.x < 128 && threadIdx.x >= off) x = sb[threadIdx.x - off];
        __syncthreads();
        if (threadIdx.x < 128) sb[threadIdx.x] += x;
        __syncthreads();
    }
    int excl = (b > 0) ? sb[b-1] : 0;
    if (i < Nn) g_rowptr[i+1] = s[threadIdx.x] + excl;
    if (i == 0) g_rowptr[0] = 0;
}

// atomic-free scatter: position = rowptr[dst] + rank
__global__ void k_scatter(const int* __restrict__ src, const int* __restrict__ dst){
    int i = blockIdx.x*blockDim.x + threadIdx.x;
    if (i < Ee){
        int p = g_rowptr[dst[i]] + g_rank[i];
        g_col[p] = src[i] * 16;      // pre-scaled uint2 row offset
    }
}

// ---------------- per-block BN coefficient computation ----------------
__device__ __forceinline__ void bn_coeffs(const float* __restrict__ stats,
                                          const float* __restrict__ gamma,
                                          const float* __restrict__ beta,
                                          float* sA, float* sB, int tid)
{
    if (tid < 64){
        float m = stats[tid]    * (1.f/Nn);
        float v = stats[64+tid] * (1.f/Nn) - m*m;
        float a = gamma[tid] * rsqrtf(v + 1e-5f);
        sA[tid] = a;
        sB[tid] = beta[tid] - m*a;
    }
}

// ---------------- aggregation: TWO nodes per warp (16 lanes x 4 halfs each),
// fp16 gather, pipelined col prefetch, half2 BN+relu, fused pooling ----------------
template<int MODE>
__global__ void __launch_bounds__(256) k_agg(const uint2* __restrict__ hh,
                                             const float* __restrict__ eps, int layer,
                                             const int* __restrict__ gid,
                                             float* __restrict__ pooled,
                                             const float* __restrict__ statsIn,
                                             const float* __restrict__ gamma,
                                             const float* __restrict__ beta)
{
    __shared__ float sA[64], sB[64];
    __shared__ float sPool[16][64];
    __shared__ int   sGid[16];
    int tid  = threadIdx.x;
    int wp   = tid >> 5;
    int lane = tid & 31;
    int half = lane >> 4;
    int hl   = lane & 15;
    int nl   = wp*2 + half;              // 0..15 node within block
    int w    = blockIdx.x*16 + nl;       // Nn % 16 == 0 -> always valid

    if (MODE){
        bn_coeffs(statsIn, gamma, beta, sA, sB, tid);
        __syncthreads();
    }

    int c0 = hl*4;
    __half2 A0 = __float2half2_rn(1.f), A1 = A0;
    __half2 B0 = __float2half2_rn(0.f), B1 = B0;
    const __half2 Z2 = __float2half2_rn(0.f);
    if (MODE){
        A0 = __floats2half2_rn(sA[c0],   sA[c0+1]);
        A1 = __floats2half2_rn(sA[c0+2], sA[c0+3]);
        B0 = __floats2half2_rn(sB[c0],   sB[c0+1]);
        B1 = __floats2half2_rn(sB[c0+2], sB[c0+3]);
    }
    float epv = 1.f + eps[layer];

    uint2 sv = hh[w*16 + hl];
    __half2 s0 = *(__half2*)&sv.x, s1 = *(__half2*)&sv.y;
    if (MODE){
        s0 = __hmax2(__hfma2(s0, A0, B0), Z2);
        s1 = __hmax2(__hfma2(s1, A1, B1), Z2);
    }
    float2 f0 = __half22float2(s0), f1 = __half22float2(s1);
    *(float2*)&sPool[nl][c0]     = f0;
    *(float2*)&sPool[nl][c0 + 2] = f1;
    if (hl == 0) sGid[nl] = gid[w];

    float ax0 = f0.x*epv, ax1 = f0.y*epv, ax2 = f1.x*epv, ax3 = f1.y*epv;
    int e = g_rowptr[w], end = g_rowptr[w+1];

    int o0=0, o1=0, o2=0, o3=0;
    bool have = (e + 4 <= end);
    if (have){ o0 = g_col[e]; o1 = g_col[e+1]; o2 = g_col[e+2]; o3 = g_col[e+3]; }
    while (have){
        int p0=0, p1=0, p2=0, p3=0;
        bool nxt = (e + 8 <= end);
        if (nxt){ p0 = g_col[e+4]; p1 = g_col[e+5]; p2 = g_col[e+6]; p3 = g_col[e+7]; }
        uint2 v0 = hh[o0+hl], v1 = hh[o1+hl], v2 = hh[o2+hl], v3 = hh[o3+hl];
        __half2 a0 = *(__half2*)&v0.x, b0 = *(__half2*)&v0.y;
        __half2 a1 = *(__half2*)&v1.x, b1 = *(__half2*)&v1.y;
        __half2 a2 = *(__half2*)&v2.x, b2 = *(__half2*)&v2.y;
        __half2 a3 = *(__half2*)&v3.x, b3 = *(__half2*)&v3.y;
        if (MODE){
            a0 = __hmax2(__hfma2(a0,A0,B0),Z2); b0 = __hmax2(__hfma2(b0,A1,B1),Z2);
            a1 = __hmax2(__hfma2(a1,A0,B0),Z2); b1 = __hmax2(__hfma2(b1,A1,B1),Z2);
            a2 = __hmax2(__hfma2(a2,A0,B0),Z2); b2 = __hmax2(__hfma2(b2,A1,B1),Z2);
            a3 = __hmax2(__hfma2(a3,A0,B0),Z2); b3 = __hmax2(__hfma2(b3,A1,B1),Z2);
        }
        float2 g0 = __half22float2(a0), h0 = __half22float2(b0);
        float2 g1 = __half22float2(a1), h1 = __half22float2(b1);
        float2 g2 = __half22float2(a2), h2 = __half22float2(b2);
        float2 g3 = __half22float2(a3), h3 = __half22float2(b3);
        ax0 += (g0.x + g1.x) + (g2.x + g3.x);
        ax1 += (g0.y + g1.y) + (g2.y + g3.y);
        ax2 += (h0.x + h1.x) + (h2.x + h3.x);
        ax3 += (h0.y + h1.y) + (h2.y + h3.y);
        o0 = p0; o1 = p1; o2 = p2; o3 = p3;
        e += 4;
        have = nxt;
    }
    for (; e < end; e++){
        uint2 v = hh[g_col[e] + hl];
        __half2 a = *(__half2*)&v.x, b = *(__half2*)&v.y;
        if (MODE){
            a = __hmax2(__hfma2(a,A0,B0),Z2);
            b = __hmax2(__hfma2(b,A1,B1),Z2);
        }
        float2 g = __half22float2(a), hq = __half22float2(b);
        ax0 += g.x; ax1 += g.y; ax2 += hq.x; ax3 += hq.y;
    }

    __half2 r0 = __floats2half2_rn(ax0, ax1);
    __half2 r1 = __floats2half2_rn(ax2, ax3);
    uint2 ov; ov.x = *(unsigned*)&r0; ov.y = *(unsigned*)&r1;
    ((uint2*)g_pre16)[w*16 + hl] = ov;

    __syncthreads();
    if (tid < 64){
        float acc = sPool[0][tid];
        int cur = sGid[0];
        #pragma unroll
        for (int r = 1; r < 16; r++){
            int g = sGid[r];
            if (g != cur){
                atomicAdd(&pooled[cur*64 + tid], acc);
                cur = g; acc = sPool[r][tid];
            } else {
                acc += sPool[r][tid];
            }
        }
        atomicAdd(&pooled[cur*64 + tid], acc);
    }
}

// ---------------- HMMA GEMM: (256 rows/block x 64) @ (64 x 64) + bias, fp16 in / fp16 out,
// fp32 accumulate, fused BN-stats; optional fused BN+relu on INPUT ----------------
template<int APPLY>
__global__ void __launch_bounds__(256, 2) k_gemm(const uint4* __restrict__ X16,
                                                 const float* __restrict__ W,
                                                 const float* __restrict__ bias,
                                                 unsigned* __restrict__ Y,   // half2 units
                                                 const float* __restrict__ statsIn,
                                                 float* __restrict__ statsOut,
                                                 const float* __restrict__ gamma,
                                                 const float* __restrict__ beta)
{
    __shared__ uint4 sX4[256*8];
    __shared__ uint4 sW4[64*8];
    __shared__ float sA[64], sB[64], sBias[64];
    __shared__ float sSum[64], sSsq[64];
    char* sX  = (char*)sX4;
    char* sWt = (char*)sW4;
    int tid = threadIdx.x;
    int rowBase = blockIdx.x * 256;
    if (tid < 64){ sSum[tid] = 0.f; sSsq[tid] = 0.f; sBias[tid] = bias[tid]; }
    if (APPLY) bn_coeffs(statsIn, gamma, beta, sA, sB, tid);

    {
        const float2* W2 = (const float2*)W;
        #pragma unroll
        for (int it = 0; it < 8; it++){
            int idx = tid + it*256;
            int k  = idx >> 5;
            int n2 = idx & 31;
            __half2 hw = __float22half2_rn(W2[idx]);
            *(unsigned*)(sWt + SW(k*128 + n2*4)) = *(unsigned*)&hw;
        }
    }
    __syncthreads();

    #pragma unroll
    for (int it = 0; it < 8; it++){
        int idx = tid + it*256;
        int r = idx >> 3;
        int c = idx & 7;
        int gr = rowBase + r;
        uint4 v = make_uint4(0,0,0,0);
        if (gr < Nn){
            v = X16[gr*8 + c];
            if (APPLY){
                __half2* ph = (__half2*)&v;
                #pragma unroll
                for (int q = 0; q < 4; q++){
                    float2 f = __half22float2(ph[q]);
                    int col = c*8 + q*2;
                    f.x = fmaxf(fmaf(f.x, sA[col],   sB[col]),   0.f);
                    f.y = fmaxf(fmaf(f.y, sA[col+1], sB[col+1]), 0.f);
                    ph[q] = __float22half2_rn(f);
                }
            }
        }
        *(uint4*)(sX + SW(r*128 + c*16)) = v;
    }
    __syncthreads();

    int wid  = tid >> 5;
    int lane = tid & 31;
    int warpRow = wid * 32;
    unsigned sXb = sptr(sX);
    unsigned sWb = sptr(sWt);

    float acc[2][8][4];
    #pragma unroll
    for (int mt = 0; mt < 2; mt++)
        #pragma unroll
        for (int nt = 0; nt < 8; nt++)
            #pragma unroll
            for (int q = 0; q < 4; q++) acc[mt][nt][q] = 0.f;

    int sel = lane >> 3;
    int lr  = lane & 7;
    #pragma unroll
    for (int ks = 0; ks < 4; ks++){
        unsigned a[2][4];
        #pragma unroll
        for (int mt = 0; mt < 2; mt++){
            int rowl = warpRow + mt*16 + lr + ((sel & 1) << 3);
            int kb   = ks*32 + ((sel >> 1) << 4);
            ldm_x4(sXb + SW(rowl*128 + kb), a[mt][0], a[mt][1], a[mt][2], a[mt][3]);
        }
        #pragma unroll
        for (int j = 0; j < 4; j++){
            int kr = ks*16 + lr + ((sel & 1) << 3);
            int nb = j*32 + ((sel >> 1) << 4);
            unsigned b0, b1, b2, b3;
            ldm_x4t(sWb + SW(kr*128 + nb), b0, b1, b2, b3);
            mma16816(acc[0][2*j],   a[0], b0, b1);
            mma16816(acc[1][2*j],   a[1], b0, b1);
            mma16816(acc[0][2*j+1], a[0], b2, b3);
            mma16816(acc[1][2*j+1], a[1], b2, b3);
        }
    }

    int g  = lane >> 2;
    int i4 = lane & 3;
    int i2 = i4 * 2;
    #pragma unroll
    for (int nt = 0; nt < 8; nt++){
        float b0f = sBias[nt*8 + i2];
        float b1f = sBias[nt*8 + i2 + 1];
        float s0 = 0.f, s1 = 0.f, q0 = 0.f, q1 = 0.f;
        #pragma unroll
        for (int mt = 0; mt < 2; mt++){
            int row0 = rowBase + warpRow + mt*16 + g;
            float d0 = acc[mt][nt][0] + b0f;
            float d1 = acc[mt][nt][1] + b1f;
            float d2 = acc[mt][nt][2] + b0f;
            float d3 = acc[mt][nt][3] + b1f;
            if (row0 < Nn){
                __half2 hv = __float22half2_rn(make_float2(d0, d1));
                Y[row0*32 + nt*4 + i4] = *(unsigned*)&hv;
                s0 += d0; s1 += d1; q0 += d0*d0; q1 += d1*d1;
            }
            if (row0 + 8 < Nn){
                __half2 hv = __float22half2_rn(make_float2(d2, d3));
                Y[(row0+8)*32 + nt*4 + i4] = *(unsigned*)&hv;
                s0 += d2; s1 += d3; q0 += d2*d2; q1 += d3*d3;
            }
        }
        #pragma unroll
        for (int off = 4; off < 32; off <<= 1){
            s0 += __shfl_xor_sync(0xffffffffu, s0, off);
            s1 += __shfl_xor_sync(0xffffffffu, s1, off);
            q0 += __shfl_xor_sync(0xffffffffu, q0, off);
            q1 += __shfl_xor_sync(0xffffffffu, q1, off);
        }
        if (lane < 4){
            atomicAdd(&sSum[nt*8 + lane*2],     s0);
            atomicAdd(&sSum[nt*8 + lane*2 + 1], s1);
            atomicAdd(&sSsq[nt*8 + lane*2],     q0);
            atomicAdd(&sSsq[nt*8 + lane*2 + 1], q1);
        }
    }
    __syncthreads();
    if (tid < 64){
        atomicAdd(&statsOut[tid],    sSum[tid]);
        atomicAdd(&statsOut[64+tid], sSsq[tid]);
    }
}

// ---------------- final-layer pooling (BN+relu fused), fp16 source ----------------
__global__ void k_pool(const __half* __restrict__ Uh, const int* __restrict__ gid,
                       float* __restrict__ pooled,
                       const float* __restrict__ statsIn,
                       const float* __restrict__ gamma,
                       const float* __restrict__ beta)
{
    __shared__ float sA[64], sB[64];
    int tid = threadIdx.x;
    bn_coeffs(statsIn, gamma, beta, sA, sB, tid);
    __syncthreads();
    int col  = tid & 63;
    int rl   = tid >> 6;
    int base = blockIdx.x * 128 + rl*32;
    float a = sA[col], b = sB[col];
    float acc = 0.f; int cur = -1;
    for (int j = 0; j < 32; j++){
        int r = base + j;
        if (r >= Nn) break;
        float x = __half2float(Uh[r*64 + col]);
        x = fmaxf(fmaf(x, a, b), 0.f);
        int g = gid[r];
        if (g != cur){
            if (cur >= 0) atomicAdd(&pooled[cur*64 + col], acc);
            cur = g; acc = x;
        } else {
            acc += x;
        }
    }
    if (cur >= 0) atomicAdd(&pooled[cur*64 + col], acc);
}

// ---------------- score = sum_i pooled_i @ Wp_i + bp_i ----------------
__global__ void k_score(const float* __restrict__ Wp, const float* __restrict__ bp,
                        float* __restrict__ out)
{
    int t = blockIdx.x*blockDim.x + threadIdx.x;
    if (t >= NG*16) return;
    int g = t >> 4, o = t & 15;
    float acc = 0.f;
    #pragma unroll
    for (int i = 0; i < NPRED; i++){
        const float* __restrict__ P  = &g_pooled[(i*NG + g)*64];
        const float* __restrict__ Wr = Wp + i*64*16 + o;
        float s = 0.f;
        #pragma unroll 16
        for (int k = 0; k < 64; k++) s = fmaf(P[k], Wr[k*16], s);
        acc += s + bp[i*16 + o];
    }
    out[t] = acc;
}

// ---------------- launch ----------------
extern "C" void kernel_launch(void* const* d_in, const int* in_sizes, int n_in,
                              void* d_out, int out_size)
{
    const float* h    = (const float*)d_in[0];
    const int*   esrc = (const int*)  d_in[1];
    const int*   edst = (const int*)  d_in[2];
    const int*   gid  = (const int*)  d_in[3];
    const float* eps  = (const float*)d_in[4];
    const float* W1   = (const float*)d_in[5];
    const float* b1   = (const float*)d_in[6];
    const float* g1   = (const float*)d_in[7];
    const float* be1  = (const float*)d_in[8];
    const float* W2   = (const float*)d_in[9];
    const float* b2   = (const float*)d_in[10];
    const float* g2   = (const float*)d_in[11];
    const float* be2  = (const float*)d_in[12];
    const float* Wp   = (const float*)d_in[13];
    const float* bp   = (const float*)d_in[14];
    float* out = (float*)d_out;

    void *p_pooled, *p_pre16, *p_t16, *p_u16, *p_h16, *p_stats;
    cudaGetSymbolAddress(&p_pooled, g_pooled);
    cudaGetSymbolAddress(&p_pre16,  g_pre16);
    cudaGetSymbolAddress(&p_t16,    g_t16);
    cudaGetSymbolAddress(&p_u16,    g_u16);
    cudaGetSymbolAddress(&p_h16,    g_h16);
    cudaGetSymbolAddress(&p_stats,  g_stats);
    float* stats  = (float*)p_stats;
    float* pooled = (float*)p_pooled;

    // CSR by destination: hist(+rank+convert), fused scan, atomic-free scatter
    k_hist<<<(Ee+255)/256, 256>>>(edst, h);
    int nb = (Nn + 1023)/1024;
    k_scan<<<nb, 1024>>>(nb);
    k_scatter<<<(Ee+255)/256, 256>>>(esrc, edst);

    int gemmB_ = (Nn + 255)/256;
    int aggB   = Nn/16;

    for (int i = 0; i < NGIN; i++){
        float* s1 = stats + (2*i)*128;
        float* s2 = stats + (2*i+1)*128;

        if (i == 0)
            k_agg<0><<<aggB, 256>>>((const uint2*)p_h16, eps, 0, gid, pooled,
                                    nullptr, nullptr, nullptr);
        else
            k_agg<1><<<aggB, 256>>>((const uint2*)p_u16, eps, i, gid,
                                    pooled + (size_t)i*NG*Dd,
                                    stats + (2*(i-1)+1)*128,
                                    g2 + (i-1)*64, be2 + (i-1)*64);

        k_gemm<0><<<gemmB_, 256>>>((const uint4*)p_pre16, W1 + i*4096, b1 + i*64,
                                   (unsigned*)p_t16, nullptr, s1, nullptr, nullptr);
        k_gemm<1><<<gemmB_, 256>>>((const uint4*)p_t16, W2 + i*4096, b2 + i*64,
                                   (unsigned*)p_u16, s1, s2, g1 + i*64, be1 + i*64);
    }

    k_pool<<<(Nn + 127)/128, 256>>>((const __half*)p_u16, gid,
                                    pooled + (size_t)NGIN*NG*Dd,
                                    stats + 7*128, g2 + 3*64, be2 + 3*64);

    k_score<<<(NG*16 + 255)/256, 256>>>(Wp, bp, out);
}